// round 1
// baseline (speedup 1.0000x reference)
#include <cuda_runtime.h>
#include <cuda_bf16.h>

// Problem constants
#define BATCH 4
#define SEQ   2048
#define DMODEL 1024
#define NHEAD 16
#define HDIM  64
#define MROWS (BATCH * SEQ)          // 8192

// Scratch (device globals; allocation-free)
__device__ float g_q[BATCH * NHEAD * SEQ * HDIM];     // [B,H,T,HD]
__device__ float g_k[BATCH * NHEAD * SEQ * HDIM];
__device__ float g_v[BATCH * NHEAD * SEQ * HDIM];
__device__ float g_attn[BATCH * SEQ * DMODEL];        // [B,T,D]

// ---------------------------------------------------------------------------
// GEMM: C[M,N] = A[M,K] @ W[K,N] + bias
// MODE 0: A = hidden_states, scatter output into g_q/g_k/g_v ([B,H,T,HD])
// MODE 1: A = g_attn, write C[row*N + col] (d_out)
// Tiling: BM=BN=128, BK=8, TM=TN=8, 256 threads.
// ---------------------------------------------------------------------------
template <int MODE>
__global__ __launch_bounds__(256) void gemm_kernel(
    const float* __restrict__ A_in,
    const float* __restrict__ W,
    const float* __restrict__ bias,
    float* __restrict__ C,
    int Kdim, int Ndim)
{
    __shared__ float As[8][128];   // transposed: As[k][m]
    __shared__ float Bs[8][128];   // Bs[k][n]

    const float* A = (MODE == 0) ? A_in : g_attn;

    const int m0 = blockIdx.y * 128;
    const int n0 = blockIdx.x * 128;
    const int tid = threadIdx.x;
    const int tx = tid & 15;          // 0..15 -> 8 cols each
    const int ty = tid >> 4;          // 0..15 -> 8 rows each

    const int aRow = tid >> 1;             // 0..127
    const int aCol = (tid & 1) << 2;       // 0 or 4
    const int bRow = tid >> 5;             // 0..7
    const int bCol = (tid & 31) << 2;      // 0..124

    float acc[8][8];
#pragma unroll
    for (int i = 0; i < 8; i++)
#pragma unroll
        for (int j = 0; j < 8; j++) acc[i][j] = 0.0f;

    const float* Ablk = A + (size_t)m0 * Kdim;

    for (int kt = 0; kt < Kdim; kt += 8) {
        float4 av = *(const float4*)&Ablk[(size_t)aRow * Kdim + kt + aCol];
        float4 bv = *(const float4*)&W[(size_t)(kt + bRow) * Ndim + n0 + bCol];
        __syncthreads();   // previous compute done reading smem
        As[aCol + 0][aRow] = av.x;
        As[aCol + 1][aRow] = av.y;
        As[aCol + 2][aRow] = av.z;
        As[aCol + 3][aRow] = av.w;
        *(float4*)&Bs[bRow][bCol] = bv;
        __syncthreads();

#pragma unroll
        for (int k = 0; k < 8; k++) {
            float4 a0 = *(const float4*)&As[k][ty * 8];
            float4 a1 = *(const float4*)&As[k][ty * 8 + 4];
            float4 b0 = *(const float4*)&Bs[k][tx * 8];
            float4 b1 = *(const float4*)&Bs[k][tx * 8 + 4];
            float ar[8] = {a0.x, a0.y, a0.z, a0.w, a1.x, a1.y, a1.z, a1.w};
            float br[8] = {b0.x, b0.y, b0.z, b0.w, b1.x, b1.y, b1.z, b1.w};
#pragma unroll
            for (int i = 0; i < 8; i++)
#pragma unroll
                for (int j = 0; j < 8; j++)
                    acc[i][j] = fmaf(ar[i], br[j], acc[i][j]);
        }
    }

    // epilogue
#pragma unroll
    for (int i = 0; i < 8; i++) {
        const int row = m0 + ty * 8 + i;
#pragma unroll
        for (int j = 0; j < 8; j++) {
            const int col = n0 + tx * 8 + j;
            const float val = acc[i][j] + bias[col];
            if (MODE == 0) {
                // scatter to q/k/v in [B,H,T,HD]
                const int which = col >> 10;       // 0=q,1=k,2=v
                const int d     = col & 1023;
                const int h     = d >> 6;
                const int hd    = d & 63;
                const int b     = row >> 11;       // / SEQ
                const int t     = row & 2047;
                const size_t idx = (((size_t)(b * NHEAD + h)) * SEQ + t) * HDIM + hd;
                float* dst = (which == 0) ? g_q : (which == 1) ? g_k : g_v;
                dst[idx] = val;
            } else {
                C[(size_t)row * Ndim + col] = val;
            }
        }
    }
}

// ---------------------------------------------------------------------------
// Causal flash attention, fp32.
// Block: 128 threads. Q tile 64 rows, K tile 64 keys, HD=64.
// Thread grid 16(tx: 4 hd/key cols) x 8(ty: 8 rows).
// smem: Qt[k][m] 16KB + KV (Kt[k][n] then V[n][d]) 16KB + S[m][n] 16KB = 48KB.
// Grid: (T/64, B*H). Skips fully-masked key tiles.
// ---------------------------------------------------------------------------
__global__ __launch_bounds__(128) void flash_kernel()
{
    __shared__ float Qt[64 * 64];
    __shared__ float KV[64 * 64];
    __shared__ float Sm[64 * 64];

    const int qTile = blockIdx.x;
    const int bh    = blockIdx.y;

    const float* Qg = g_q + (size_t)bh * SEQ * HDIM;
    const float* Kg = g_k + (size_t)bh * SEQ * HDIM;
    const float* Vg = g_v + (size_t)bh * SEQ * HDIM;

    const int tid = threadIdx.x;
    const int tx = tid & 15;   // 4 cols
    const int ty = tid >> 4;   // 8 rows
    const int q0 = qTile * 64;

    // Load Q tile transposed: Qt[hd][m].
    // Mapping r = idx&63 (row), c4 = (idx>>6)*4 -> conflict-free smem stores
    // (gmem reads are strided; acceptable traffic).
#pragma unroll
    for (int it = 0; it < 8; it++) {
        const int idx = tid + it * 128;
        const int r   = idx & 63;
        const int c4  = (idx >> 6) << 2;
        float4 v = *(const float4*)&Qg[(size_t)(q0 + r) * HDIM + c4];
        Qt[(c4 + 0) * 64 + r] = v.x;
        Qt[(c4 + 1) * 64 + r] = v.y;
        Qt[(c4 + 2) * 64 + r] = v.z;
        Qt[(c4 + 3) * 64 + r] = v.w;
    }

    float accO[8][4];
    float mrow[8], lrow[8];
#pragma unroll
    for (int i = 0; i < 8; i++) {
        mrow[i] = -1e30f;
        lrow[i] = 0.0f;
#pragma unroll
        for (int j = 0; j < 4; j++) accO[i][j] = 0.0f;
    }

    for (int kt = 0; kt <= qTile; kt++) {
        const int k0 = kt * 64;
        __syncthreads();   // prev PV done with KV; Qt visible (first iter)

        // Load K tile transposed: Kt[hd][n]
#pragma unroll
        for (int it = 0; it < 8; it++) {
            const int idx = tid + it * 128;
            const int r   = idx & 63;
            const int c4  = (idx >> 6) << 2;
            float4 v = *(const float4*)&Kg[(size_t)(k0 + r) * HDIM + c4];
            KV[(c4 + 0) * 64 + r] = v.x;
            KV[(c4 + 1) * 64 + r] = v.y;
            KV[(c4 + 2) * 64 + r] = v.z;
            KV[(c4 + 3) * 64 + r] = v.w;
        }
        __syncthreads();

        // S = Q @ K^T (64 k-steps)
        float accS[8][4];
#pragma unroll
        for (int i = 0; i < 8; i++)
#pragma unroll
            for (int j = 0; j < 4; j++) accS[i][j] = 0.0f;

#pragma unroll 8
        for (int k = 0; k < 64; k++) {
            float4 a0 = *(const float4*)&Qt[k * 64 + ty * 8];
            float4 a1 = *(const float4*)&Qt[k * 64 + ty * 8 + 4];
            float4 b  = *(const float4*)&KV[k * 64 + tx * 4];
            float ar[8] = {a0.x, a0.y, a0.z, a0.w, a1.x, a1.y, a1.z, a1.w};
            float br[4] = {b.x, b.y, b.z, b.w};
#pragma unroll
            for (int i = 0; i < 8; i++)
#pragma unroll
                for (int j = 0; j < 4; j++)
                    accS[i][j] = fmaf(ar[i], br[j], accS[i][j]);
        }

        // scale + causal mask (diag tile only)
        const float scale = 0.125f;   // 1/sqrt(64)
        if (kt == qTile) {
#pragma unroll
            for (int i = 0; i < 8; i++) {
                const int qg = ty * 8 + i;
#pragma unroll
                for (int j = 0; j < 4; j++) {
                    const int kg = tx * 4 + j;
                    accS[i][j] = (kg > qg) ? -1e30f : accS[i][j] * scale;
                }
            }
        } else {
#pragma unroll
            for (int i = 0; i < 8; i++)
#pragma unroll
                for (int j = 0; j < 4; j++) accS[i][j] *= scale;
        }

        // online softmax (row reductions across the 16 lanes sharing a row)
#pragma unroll
        for (int i = 0; i < 8; i++) {
            float rm = fmaxf(fmaxf(accS[i][0], accS[i][1]),
                             fmaxf(accS[i][2], accS[i][3]));
#pragma unroll
            for (int s = 8; s > 0; s >>= 1)
                rm = fmaxf(rm, __shfl_xor_sync(0xffffffffu, rm, s, 16));
            const float mn = fmaxf(mrow[i], rm);
            const float al = __expf(mrow[i] - mn);
            float p[4], rs = 0.0f;
#pragma unroll
            for (int j = 0; j < 4; j++) {
                p[j] = __expf(accS[i][j] - mn);
                rs += p[j];
            }
#pragma unroll
            for (int s = 8; s > 0; s >>= 1)
                rs += __shfl_xor_sync(0xffffffffu, rs, s, 16);
            lrow[i] = lrow[i] * al + rs;
            mrow[i] = mn;
#pragma unroll
            for (int j = 0; j < 4; j++) {
                accO[i][j] *= al;
                Sm[(ty * 8 + i) * 64 + tx * 4 + j] = p[j];
            }
        }
        __syncthreads();   // K reads done + Sm writes issued

        // Load V tile [n][d] (coalesced)
#pragma unroll
        for (int it = 0; it < 8; it++) {
            const int idx = tid + it * 128;
            const int r   = idx >> 4;
            const int c4  = (idx & 15) << 2;
            *(float4*)&KV[r * 64 + c4] =
                *(const float4*)&Vg[(size_t)(k0 + r) * HDIM + c4];
        }
        __syncthreads();   // V + Sm visible

        // O += P @ V
#pragma unroll 8
        for (int n = 0; n < 64; n++) {
            float4 b = *(const float4*)&KV[n * 64 + tx * 4];
            float br[4] = {b.x, b.y, b.z, b.w};
#pragma unroll
            for (int i = 0; i < 8; i++) {
                const float a = Sm[(ty * 8 + i) * 64 + n];
#pragma unroll
                for (int j = 0; j < 4; j++)
                    accO[i][j] = fmaf(a, br[j], accO[i][j]);
            }
        }
    }

    // write output merged-head [B,T,D]
    const int b = bh / NHEAD;
    const int h = bh % NHEAD;
#pragma unroll
    for (int i = 0; i < 8; i++) {
        const int t = q0 + ty * 8 + i;
        const float inv_l = 1.0f / lrow[i];
        float* dst = g_attn + ((size_t)(b * SEQ + t)) * DMODEL + h * HDIM + tx * 4;
#pragma unroll
        for (int j = 0; j < 4; j++)
            dst[j] = accO[i][j] * inv_l;
    }
}

// ---------------------------------------------------------------------------
// kernel_launch
// inputs: 0 hidden_states [B,T,D] f32, 1 w_attn [D,3D], 2 b_attn [3D],
//         3 w_proj [D,D], 4 b_proj [D]; output [B,T,D] f32
// ---------------------------------------------------------------------------
extern "C" void kernel_launch(void* const* d_in, const int* in_sizes, int n_in,
                              void* d_out, int out_size)
{
    const float* hidden = (const float*)d_in[0];
    const float* w_attn = (const float*)d_in[1];
    const float* b_attn = (const float*)d_in[2];
    const float* w_proj = (const float*)d_in[3];
    const float* b_proj = (const float*)d_in[4];
    float* out = (float*)d_out;

    // 1) QKV GEMM + bias + head split
    gemm_kernel<0><<<dim3(3 * DMODEL / 128, MROWS / 128), 256>>>(
        hidden, w_attn, b_attn, nullptr, DMODEL, 3 * DMODEL);

    // 2) causal flash attention
    flash_kernel<<<dim3(SEQ / 64, BATCH * NHEAD), 128>>>();

    // 3) output projection + bias
    gemm_kernel<1><<<dim3(DMODEL / 128, MROWS / 128), 256>>>(
        nullptr, w_proj, b_proj, out, DMODEL, DMODEL);
}

// round 4
// speedup vs baseline: 2.8771x; 2.8771x over previous
#include <cuda_runtime.h>
#include <cuda_bf16.h>

// Problem constants
#define BATCH 4
#define SEQ   2048
#define DMODEL 1024
#define NHEAD 16
#define HDIM  64
#define MROWS (BATCH * SEQ)          // 8192

// Scratch (device globals; allocation-free)
__device__ float g_q[BATCH * NHEAD * SEQ * HDIM];     // [B,H,T,HD]
__device__ float g_k[BATCH * NHEAD * SEQ * HDIM];
__device__ float g_v[BATCH * NHEAD * SEQ * HDIM];
__device__ float g_attn[BATCH * SEQ * DMODEL];        // [B,T,D]

// ---------------------------------------------------------------------------
// helpers
// ---------------------------------------------------------------------------
__device__ __forceinline__ unsigned f2tf(float x) {
    unsigned r;
    asm("cvt.rna.tf32.f32 %0, %1;" : "=r"(r) : "f"(x));
    return r;
}

__device__ __forceinline__ void mma_tf32(float* d, const unsigned* a, const unsigned* b) {
    asm volatile(
        "mma.sync.aligned.m16n8k8.row.col.f32.tf32.tf32.f32 "
        "{%0,%1,%2,%3},{%4,%5,%6,%7},{%8,%9},{%0,%1,%2,%3};\n"
        : "+f"(d[0]), "+f"(d[1]), "+f"(d[2]), "+f"(d[3])
        : "r"(a[0]), "r"(a[1]), "r"(a[2]), "r"(a[3]), "r"(b[0]), "r"(b[1]));
}

__device__ __forceinline__ void cp_async16(void* smem, const void* g) {
    unsigned s = (unsigned)__cvta_generic_to_shared(smem);
    asm volatile("cp.async.cg.shared.global [%0], [%1], 16;\n" :: "r"(s), "l"(g));
}
#define CP_COMMIT() asm volatile("cp.async.commit_group;\n" ::: "memory")
#define CP_WAIT(n)  asm volatile("cp.async.wait_group %0;\n" :: "n"(n) : "memory")

// ---------------------------------------------------------------------------
// TF32 tensor-core GEMM: C[M,N] = A[M,K] @ W[K,N] + bias
// MODE 0: A = hidden_states, scatter into g_q/g_k/g_v ([B,H,T,HD])
// MODE 1: A = g_attn, write C (d_out)
// Block tile 128x128x16, 8 warps (warp tile 32x64), cp.async double buffer.
// smem strides: A 20 (bank-unique 4m+k), B 136 (bank-unique 8k+n).
// ---------------------------------------------------------------------------
template <int MODE>
__global__ __launch_bounds__(256) void gemm_tf32(
    const float* __restrict__ A_in,
    const float* __restrict__ W,
    const float* __restrict__ bias,
    float* __restrict__ C,
    int Kdim, int Ndim)
{
    __shared__ float As[2][128 * 20];
    __shared__ float Bs[2][16 * 136];

    const float* A = (MODE == 0) ? A_in : g_attn;

    const int m0 = blockIdx.y * 128;
    const int n0 = blockIdx.x * 128;
    const int tid  = threadIdx.x;
    const int lane = tid & 31;
    const int wid  = tid >> 5;
    const int wr = (wid & 3) * 32;   // warp row offset (4 warps in M)
    const int wc = (wid >> 2) * 64;  // warp col offset (2 warps in N)

    float acc[2][8][4];
#pragma unroll
    for (int i = 0; i < 2; i++)
#pragma unroll
        for (int j = 0; j < 8; j++)
#pragma unroll
            for (int r = 0; r < 4; r++) acc[i][j][r] = 0.0f;

    // tile loaders: A 128x16 (512 f4), B 16x128 (512 f4); 2 f4 each per thread
#define LOAD_A(KT_, ST_)                                                        \
    _Pragma("unroll")                                                           \
    for (int i_ = 0; i_ < 2; i_++) {                                            \
        int idx_ = tid + i_ * 256;                                              \
        int row_ = idx_ >> 2, c4_ = (idx_ & 3) << 2;                            \
        cp_async16(&As[ST_][row_ * 20 + c4_],                                   \
                   &A[(size_t)(m0 + row_) * Kdim + (KT_) + c4_]);               \
    }
#define LOAD_B(KT_, ST_)                                                        \
    _Pragma("unroll")                                                           \
    for (int i_ = 0; i_ < 2; i_++) {                                            \
        int idx_ = tid + i_ * 256;                                              \
        int kr_ = idx_ >> 5, n4_ = (idx_ & 31) << 2;                            \
        cp_async16(&Bs[ST_][kr_ * 136 + n4_],                                   \
                   &W[(size_t)((KT_) + kr_) * Ndim + n0 + n4_]);                \
    }

    LOAD_A(0, 0);
    LOAD_B(0, 0);
    CP_COMMIT();

    const int KT = Kdim >> 4;
    int st = 0;
    for (int kt = 0; kt < KT; kt++) {
        if (kt + 1 < KT) {
            LOAD_A((kt + 1) << 4, st ^ 1);
            LOAD_B((kt + 1) << 4, st ^ 1);
            CP_COMMIT();
            CP_WAIT(1);
        } else {
            CP_WAIT(0);
        }
        __syncthreads();

        const float* as = As[st];
        const float* bs = Bs[st];
#pragma unroll
        for (int ks = 0; ks < 2; ks++) {
            const int ko = ks * 8;
            unsigned af[2][4], bf[8][2];
#pragma unroll
            for (int i = 0; i < 2; i++) {
                const int r = wr + i * 16 + (lane >> 2);
                af[i][0] = f2tf(as[r * 20 + ko + (lane & 3)]);
                af[i][1] = f2tf(as[(r + 8) * 20 + ko + (lane & 3)]);
                af[i][2] = f2tf(as[r * 20 + ko + (lane & 3) + 4]);
                af[i][3] = f2tf(as[(r + 8) * 20 + ko + (lane & 3) + 4]);
            }
#pragma unroll
            for (int j = 0; j < 8; j++) {
                const int col = wc + j * 8 + (lane >> 2);
                bf[j][0] = f2tf(bs[(ko + (lane & 3)) * 136 + col]);
                bf[j][1] = f2tf(bs[(ko + (lane & 3) + 4) * 136 + col]);
            }
#pragma unroll
            for (int i = 0; i < 2; i++)
#pragma unroll
                for (int j = 0; j < 8; j++) mma_tf32(acc[i][j], af[i], bf[j]);
        }
        __syncthreads();
        st ^= 1;
    }

    // epilogue: c0,c1 = (row, 2c),(row, 2c+1); c2,c3 at row+8
#pragma unroll
    for (int i = 0; i < 2; i++) {
#pragma unroll
        for (int rr = 0; rr < 2; rr++) {
            const int row = m0 + wr + i * 16 + (lane >> 2) + rr * 8;
#pragma unroll
            for (int j = 0; j < 8; j++) {
                const int col = n0 + wc + j * 8 + (lane & 3) * 2;
                const float v0 = acc[i][j][rr * 2 + 0] + bias[col];
                const float v1 = acc[i][j][rr * 2 + 1] + bias[col + 1];
                if (MODE == 0) {
                    const int which = col >> 10;
                    const int d  = col & 1023;
                    const int h  = d >> 6;
                    const int hd = d & 63;
                    const int b  = row >> 11;
                    const int t  = row & 2047;
                    float* dst = (which == 0) ? g_q : (which == 1) ? g_k : g_v;
                    const size_t idx =
                        (((size_t)(b * NHEAD + h)) * SEQ + t) * HDIM + hd;
                    *(float2*)&dst[idx] = make_float2(v0, v1);
                } else {
                    *(float2*)&C[(size_t)row * Ndim + col] = make_float2(v0, v1);
                }
            }
        }
    }
#undef LOAD_A
#undef LOAD_B
}

// ---------------------------------------------------------------------------
// Causal flash attention, TF32 tensor cores.
// Block 128 threads (4 warps), Q tile 64 (16 rows/warp), key tile 64, HD=64.
// smem: KtSm (K^T [hd][key] stride 72, aliased as P [q][key] stride 68) + Vs.
// Per-iter: V cp.async prefetch under S-matmul; K transposed at load.
// ---------------------------------------------------------------------------
__global__ __launch_bounds__(128) void flash_tc()
{
    __shared__ float KtSm[64 * 72];   // 18 KB
    __shared__ float Vs[64 * 72];     // 18 KB

    const int qTile = blockIdx.x;
    const int bh    = blockIdx.y;

    const float* Qg = g_q + (size_t)bh * SEQ * HDIM;
    const float* Kg = g_k + (size_t)bh * SEQ * HDIM;
    const float* Vg = g_v + (size_t)bh * SEQ * HDIM;

    const int tid  = threadIdx.x;
    const int lane = tid & 31;
    const int wid  = tid >> 5;
    const int q0   = qTile * 64;
    const int qr   = q0 + wid * 16 + (lane >> 2);

    // preload Q fragments (A-operand, 8 k-steps over HD=64)
    unsigned qf[8][4];
#pragma unroll
    for (int ks = 0; ks < 8; ks++) {
        const int k = ks * 8 + (lane & 3);
        qf[ks][0] = f2tf(Qg[(size_t)qr * HDIM + k]);
        qf[ks][1] = f2tf(Qg[(size_t)(qr + 8) * HDIM + k]);
        qf[ks][2] = f2tf(Qg[(size_t)qr * HDIM + k + 4]);
        qf[ks][3] = f2tf(Qg[(size_t)(qr + 8) * HDIM + k + 4]);
    }

    float oacc[8][4];
#pragma unroll
    for (int j = 0; j < 8; j++)
#pragma unroll
        for (int r = 0; r < 4; r++) oacc[j][r] = 0.0f;
    float m0r = -1e30f, m1r = -1e30f, l0r = 0.0f, l1r = 0.0f;

    for (int kt = 0; kt <= qTile; kt++) {
        const int k0 = kt * 64;

        // V prefetch (natural [key][hd] layout, stride 72)
#pragma unroll
        for (int it = 0; it < 8; it++) {
            const int idx = tid + it * 128;
            const int r = idx >> 4, c4 = (idx & 15) << 2;
            cp_async16(&Vs[r * 72 + c4], &Vg[(size_t)(k0 + r) * HDIM + c4]);
        }
        CP_COMMIT();

        // K transpose load: [key][hd] -> KtSm[hd][key] (stride 72)
#pragma unroll
        for (int it = 0; it < 8; it++) {
            const int idx = tid + it * 128;
            const int r = idx & 63, c4 = (idx >> 6) << 2;
            float4 v = *(const float4*)&Kg[(size_t)(k0 + r) * HDIM + c4];
            KtSm[(c4 + 0) * 72 + r] = v.x;
            KtSm[(c4 + 1) * 72 + r] = v.y;
            KtSm[(c4 + 2) * 72 + r] = v.z;
            KtSm[(c4 + 3) * 72 + r] = v.w;
        }
        __syncthreads();

        // S = Q @ K^T
        float sacc[8][4];
#pragma unroll
        for (int j = 0; j < 8; j++)
#pragma unroll
            for (int r = 0; r < 4; r++) sacc[j][r] = 0.0f;

#pragma unroll
        for (int ks = 0; ks < 8; ks++) {
            const int ko = ks * 8;
            unsigned bf[8][2];
#pragma unroll
            for (int j = 0; j < 8; j++) {
                const int key = j * 8 + (lane >> 2);
                bf[j][0] = f2tf(KtSm[(ko + (lane & 3)) * 72 + key]);
                bf[j][1] = f2tf(KtSm[(ko + (lane & 3) + 4) * 72 + key]);
            }
#pragma unroll
            for (int j = 0; j < 8; j++) mma_tf32(sacc[j], qf[ks], bf[j]);
        }

        // scale + causal mask (diag tile only)
        const float scl = 0.125f;   // 1/sqrt(64)
        if (kt == qTile) {
            const int r0 = wid * 16 + (lane >> 2);
            const int r1 = r0 + 8;
#pragma unroll
            for (int j = 0; j < 8; j++) {
                const int c = j * 8 + 2 * (lane & 3);
                sacc[j][0] = (c     > r0) ? -1e30f : sacc[j][0] * scl;
                sacc[j][1] = (c + 1 > r0) ? -1e30f : sacc[j][1] * scl;
                sacc[j][2] = (c     > r1) ? -1e30f : sacc[j][2] * scl;
                sacc[j][3] = (c + 1 > r1) ? -1e30f : sacc[j][3] * scl;
            }
        } else {
#pragma unroll
            for (int j = 0; j < 8; j++)
#pragma unroll
                for (int r = 0; r < 4; r++) sacc[j][r] *= scl;
        }

        // online softmax: row r = lane>>2 owned by 4-lane group (xor 1,2)
        float rm0 = -1e30f, rm1 = -1e30f;
#pragma unroll
        for (int j = 0; j < 8; j++) {
            rm0 = fmaxf(rm0, fmaxf(sacc[j][0], sacc[j][1]));
            rm1 = fmaxf(rm1, fmaxf(sacc[j][2], sacc[j][3]));
        }
#pragma unroll
        for (int s = 1; s < 4; s <<= 1) {
            rm0 = fmaxf(rm0, __shfl_xor_sync(0xffffffffu, rm0, s));
            rm1 = fmaxf(rm1, __shfl_xor_sync(0xffffffffu, rm1, s));
        }
        const float mn0 = fmaxf(m0r, rm0);
        const float mn1 = fmaxf(m1r, rm1);
        const float al0 = __expf(m0r - mn0);
        const float al1 = __expf(m1r - mn1);
        float rs0 = 0.0f, rs1 = 0.0f;
#pragma unroll
        for (int j = 0; j < 8; j++) {
            sacc[j][0] = __expf(sacc[j][0] - mn0);
            sacc[j][1] = __expf(sacc[j][1] - mn0);
            sacc[j][2] = __expf(sacc[j][2] - mn1);
            sacc[j][3] = __expf(sacc[j][3] - mn1);
            rs0 += sacc[j][0] + sacc[j][1];
            rs1 += sacc[j][2] + sacc[j][3];
        }
#pragma unroll
        for (int s = 1; s < 4; s <<= 1) {
            rs0 += __shfl_xor_sync(0xffffffffu, rs0, s);
            rs1 += __shfl_xor_sync(0xffffffffu, rs1, s);
        }
        l0r = l0r * al0 + rs0;
        l1r = l1r * al1 + rs1;
        m0r = mn0;
        m1r = mn1;
#pragma unroll
        for (int j = 0; j < 8; j++) {
            oacc[j][0] *= al0;
            oacc[j][1] *= al0;
            oacc[j][2] *= al1;
            oacc[j][3] *= al1;
        }
        __syncthreads();   // all warps done reading Kt before aliasing as Sm

        // store P -> Sm (stride 68; rows warp-private but buffer shared)
        float* Sm = KtSm;
        const int pr0 = wid * 16 + (lane >> 2);
#pragma unroll
        for (int j = 0; j < 8; j++) {
            const int c = j * 8 + 2 * (lane & 3);
            *(float2*)&Sm[pr0 * 68 + c]       = make_float2(sacc[j][0], sacc[j][1]);
            *(float2*)&Sm[(pr0 + 8) * 68 + c] = make_float2(sacc[j][2], sacc[j][3]);
        }
        CP_WAIT(0);
        __syncthreads();   // Sm visible + V ready

        // O += P @ V
#pragma unroll
        for (int ks = 0; ks < 8; ks++) {
            const int ko = ks * 8;
            unsigned af[4];
            af[0] = f2tf(Sm[pr0 * 68 + ko + (lane & 3)]);
            af[1] = f2tf(Sm[(pr0 + 8) * 68 + ko + (lane & 3)]);
            af[2] = f2tf(Sm[pr0 * 68 + ko + (lane & 3) + 4]);
            af[3] = f2tf(Sm[(pr0 + 8) * 68 + ko + (lane & 3) + 4]);
            unsigned bf[8][2];
#pragma unroll
            for (int j = 0; j < 8; j++) {
                const int n = j * 8 + (lane >> 2);
                bf[j][0] = f2tf(Vs[(ko + (lane & 3)) * 72 + n]);
                bf[j][1] = f2tf(Vs[(ko + (lane & 3) + 4) * 72 + n]);
            }
#pragma unroll
            for (int j = 0; j < 8; j++) mma_tf32(oacc[j], af, bf[j]);
        }
        __syncthreads();   // done with Vs/Sm before next iteration overwrites
    }

    // write merged-head output [B,T,D]
    const int b = bh >> 4;
    const int h = bh & 15;
    const float il0 = 1.0f / l0r;
    const float il1 = 1.0f / l1r;
    const int t0 = q0 + wid * 16 + (lane >> 2);
    float* base0 = g_attn + ((size_t)(b * SEQ + t0)) * DMODEL + h * HDIM;
    float* base1 = g_attn + ((size_t)(b * SEQ + t0 + 8)) * DMODEL + h * HDIM;
#pragma unroll
    for (int j = 0; j < 8; j++) {
        const int c = j * 8 + 2 * (lane & 3);
        *(float2*)&base0[c] = make_float2(oacc[j][0] * il0, oacc[j][1] * il0);
        *(float2*)&base1[c] = make_float2(oacc[j][2] * il1, oacc[j][3] * il1);
    }
}

// ---------------------------------------------------------------------------
// kernel_launch
// inputs: 0 hidden_states [B,T,D] f32, 1 w_attn [D,3D], 2 b_attn [3D],
//         3 w_proj [D,D], 4 b_proj [D]; output [B,T,D] f32
// ---------------------------------------------------------------------------
extern "C" void kernel_launch(void* const* d_in, const int* in_sizes, int n_in,
                              void* d_out, int out_size)
{
    const float* hidden = (const float*)d_in[0];
    const float* w_attn = (const float*)d_in[1];
    const float* b_attn = (const float*)d_in[2];
    const float* w_proj = (const float*)d_in[3];
    const float* b_proj = (const float*)d_in[4];
    float* out = (float*)d_out;

    // 1) QKV GEMM + bias + head split (TF32 tensor cores)
    gemm_tf32<0><<<dim3(3 * DMODEL / 128, MROWS / 128), 256>>>(
        hidden, w_attn, b_attn, nullptr, DMODEL, 3 * DMODEL);

    // 2) causal flash attention (TF32 tensor cores)
    flash_tc<<<dim3(SEQ / 64, BATCH * NHEAD), 128>>>();

    // 3) output projection + bias (TF32 tensor cores)
    gemm_tf32<1><<<dim3(DMODEL / 128, MROWS / 128), 256>>>(
        nullptr, w_proj, b_proj, out, DMODEL, DMODEL);
}

// round 5
// speedup vs baseline: 3.1167x; 1.0833x over previous
#include <cuda_runtime.h>
#include <cuda_bf16.h>

// Problem constants
#define BATCH 4
#define SEQ   2048
#define DMODEL 1024
#define NHEAD 16
#define HDIM  64
#define MROWS (BATCH * SEQ)          // 8192

// Scratch (device globals; allocation-free)
__device__ float g_q[BATCH * NHEAD * SEQ * HDIM];     // [B,H,T,HD]  (tf32-rounded)
__device__ float g_k[BATCH * NHEAD * SEQ * HDIM];
__device__ float g_v[BATCH * NHEAD * SEQ * HDIM];
__device__ float g_attn[BATCH * SEQ * DMODEL];        // [B,T,D]     (tf32-rounded)
__device__ float g_hid[MROWS * DMODEL];               // rounded hidden_states
__device__ float g_wqkv[DMODEL * 3 * DMODEL];         // rounded w_attn
__device__ float g_wp[DMODEL * DMODEL];               // rounded w_proj

// ---------------------------------------------------------------------------
// helpers
// ---------------------------------------------------------------------------
__device__ __forceinline__ unsigned f2tf(float x) {
    unsigned r;
    asm("cvt.rna.tf32.f32 %0, %1;" : "=r"(r) : "f"(x));
    return r;
}
__device__ __forceinline__ float f2tff(float x) { return __uint_as_float(f2tf(x)); }

__device__ __forceinline__ void mma_tf32(float* d, const unsigned* a, const unsigned* b) {
    asm volatile(
        "mma.sync.aligned.m16n8k8.row.col.f32.tf32.tf32.f32 "
        "{%0,%1,%2,%3},{%4,%5,%6,%7},{%8,%9},{%0,%1,%2,%3};\n"
        : "+f"(d[0]), "+f"(d[1]), "+f"(d[2]), "+f"(d[3])
        : "r"(a[0]), "r"(a[1]), "r"(a[2]), "r"(a[3]), "r"(b[0]), "r"(b[1]));
}

__device__ __forceinline__ void cp_async16(void* smem, const void* g) {
    unsigned s = (unsigned)__cvta_generic_to_shared(smem);
    asm volatile("cp.async.cg.shared.global [%0], [%1], 16;\n" :: "r"(s), "l"(g));
}
#define CP_COMMIT() asm volatile("cp.async.commit_group;\n" ::: "memory")
#define CP_WAIT(n)  asm volatile("cp.async.wait_group %0;\n" :: "n"(n) : "memory")

// ---------------------------------------------------------------------------
// Prepass: round fp32 -> tf32-valued fp32 (vectorized)
// ---------------------------------------------------------------------------
__global__ __launch_bounds__(256) void round_tf32_kernel(
    const float* __restrict__ src, float* __restrict__ dst, int n4)
{
    int i = blockIdx.x * blockDim.x + threadIdx.x;
    if (i < n4) {
        float4 v = ((const float4*)src)[i];
        v.x = f2tff(v.x); v.y = f2tff(v.y); v.z = f2tff(v.z); v.w = f2tff(v.w);
        ((float4*)dst)[i] = v;
    }
}

// ---------------------------------------------------------------------------
// TF32 tensor-core GEMM: C[M,N] = A[M,K] @ W[K,N] + bias
// Inputs pre-rounded -> zero cvt in the mainloop.
// MODE 0: A = g_hid, W = g_wqkv, scatter rounded into g_q/g_k/g_v
// MODE 1: A = g_attn, W = g_wp, write fp32 C (d_out)
// Block tile 128x128x16, 8 warps (warp tile 32x64), cp.async double buffer.
// ---------------------------------------------------------------------------
template <int MODE>
__global__ __launch_bounds__(256) void gemm_tf32(
    const float* __restrict__ bias,
    float* __restrict__ C,
    int Kdim, int Ndim)
{
    __shared__ float As[2][128 * 20];
    __shared__ float Bs[2][16 * 136];

    const float* A = (MODE == 0) ? g_hid : g_attn;
    const float* W = (MODE == 0) ? g_wqkv : g_wp;

    const int m0 = blockIdx.y * 128;
    const int n0 = blockIdx.x * 128;
    const int tid  = threadIdx.x;
    const int lane = tid & 31;
    const int wid  = tid >> 5;
    const int wr = (wid & 3) * 32;   // warp row offset (4 warps in M)
    const int wc = (wid >> 2) * 64;  // warp col offset (2 warps in N)

    float acc[2][8][4];
#pragma unroll
    for (int i = 0; i < 2; i++)
#pragma unroll
        for (int j = 0; j < 8; j++)
#pragma unroll
            for (int r = 0; r < 4; r++) acc[i][j][r] = 0.0f;

#define LOAD_A(KT_, ST_)                                                        \
    _Pragma("unroll")                                                           \
    for (int i_ = 0; i_ < 2; i_++) {                                            \
        int idx_ = tid + i_ * 256;                                              \
        int row_ = idx_ >> 2, c4_ = (idx_ & 3) << 2;                            \
        cp_async16(&As[ST_][row_ * 20 + c4_],                                   \
                   &A[(size_t)(m0 + row_) * Kdim + (KT_) + c4_]);               \
    }
#define LOAD_B(KT_, ST_)                                                        \
    _Pragma("unroll")                                                           \
    for (int i_ = 0; i_ < 2; i_++) {                                            \
        int idx_ = tid + i_ * 256;                                              \
        int kr_ = idx_ >> 5, n4_ = (idx_ & 31) << 2;                            \
        cp_async16(&Bs[ST_][kr_ * 136 + n4_],                                   \
                   &W[(size_t)((KT_) + kr_) * Ndim + n0 + n4_]);                \
    }

    LOAD_A(0, 0);
    LOAD_B(0, 0);
    CP_COMMIT();

    const int KT = Kdim >> 4;
    int st = 0;
    for (int kt = 0; kt < KT; kt++) {
        if (kt + 1 < KT) {
            LOAD_A((kt + 1) << 4, st ^ 1);
            LOAD_B((kt + 1) << 4, st ^ 1);
            CP_COMMIT();
            CP_WAIT(1);
        } else {
            CP_WAIT(0);
        }
        __syncthreads();

        const float* as = As[st];
        const float* bs = Bs[st];
#pragma unroll
        for (int ks = 0; ks < 2; ks++) {
            const int ko = ks * 8;
            unsigned af[2][4], bf[8][2];
#pragma unroll
            for (int i = 0; i < 2; i++) {
                const int r = wr + i * 16 + (lane >> 2);
                af[i][0] = __float_as_uint(as[r * 20 + ko + (lane & 3)]);
                af[i][1] = __float_as_uint(as[(r + 8) * 20 + ko + (lane & 3)]);
                af[i][2] = __float_as_uint(as[r * 20 + ko + (lane & 3) + 4]);
                af[i][3] = __float_as_uint(as[(r + 8) * 20 + ko + (lane & 3) + 4]);
            }
#pragma unroll
            for (int j = 0; j < 8; j++) {
                const int col = wc + j * 8 + (lane >> 2);
                bf[j][0] = __float_as_uint(bs[(ko + (lane & 3)) * 136 + col]);
                bf[j][1] = __float_as_uint(bs[(ko + (lane & 3) + 4) * 136 + col]);
            }
#pragma unroll
            for (int i = 0; i < 2; i++)
#pragma unroll
                for (int j = 0; j < 8; j++) mma_tf32(acc[i][j], af[i], bf[j]);
        }
        __syncthreads();
        st ^= 1;
    }

    // epilogue
#pragma unroll
    for (int i = 0; i < 2; i++) {
#pragma unroll
        for (int rr = 0; rr < 2; rr++) {
            const int row = m0 + wr + i * 16 + (lane >> 2) + rr * 8;
#pragma unroll
            for (int j = 0; j < 8; j++) {
                const int col = n0 + wc + j * 8 + (lane & 3) * 2;
                const float v0 = acc[i][j][rr * 2 + 0] + bias[col];
                const float v1 = acc[i][j][rr * 2 + 1] + bias[col + 1];
                if (MODE == 0) {
                    const int which = col >> 10;
                    const int d  = col & 1023;
                    const int h  = d >> 6;
                    const int hd = d & 63;
                    const int b  = row >> 11;
                    const int t  = row & 2047;
                    float* dst = (which == 0) ? g_q : (which == 1) ? g_k : g_v;
                    const size_t idx =
                        (((size_t)(b * NHEAD + h)) * SEQ + t) * HDIM + hd;
                    *(float2*)&dst[idx] = make_float2(f2tff(v0), f2tff(v1));
                } else {
                    *(float2*)&C[(size_t)row * Ndim + col] = make_float2(v0, v1);
                }
            }
        }
    }
#undef LOAD_A
#undef LOAD_B
}

// ---------------------------------------------------------------------------
// Causal flash attention, TF32 tensor cores, zero-cvt mainloop.
// Block 128 threads (4 warps), Q tile 64 (16 rows/warp), key tile 64, HD=64.
// P C-frag -> A-frag via warp shuffles (no smem round-trip).
// smem: Kt (K^T) 18KB + Vs 18KB. 3 syncs/tile.
// ---------------------------------------------------------------------------
__global__ __launch_bounds__(128) void flash_tc()
{
    __shared__ float Kt[64 * 72];   // 18 KB
    __shared__ float Vs[64 * 72];   // 18 KB

    const int qTile = blockIdx.x;
    const int bh    = blockIdx.y;

    const float* Qg = g_q + (size_t)bh * SEQ * HDIM;
    const float* Kg = g_k + (size_t)bh * SEQ * HDIM;
    const float* Vg = g_v + (size_t)bh * SEQ * HDIM;

    const int tid  = threadIdx.x;
    const int lane = tid & 31;
    const int wid  = tid >> 5;
    const int q0   = qTile * 64;
    const int qr   = q0 + wid * 16 + (lane >> 2);

    // preload Q fragments (pre-rounded; plain bit loads)
    unsigned qf[8][4];
#pragma unroll
    for (int ks = 0; ks < 8; ks++) {
        const int k = ks * 8 + (lane & 3);
        qf[ks][0] = __float_as_uint(Qg[(size_t)qr * HDIM + k]);
        qf[ks][1] = __float_as_uint(Qg[(size_t)(qr + 8) * HDIM + k]);
        qf[ks][2] = __float_as_uint(Qg[(size_t)qr * HDIM + k + 4]);
        qf[ks][3] = __float_as_uint(Qg[(size_t)(qr + 8) * HDIM + k + 4]);
    }

    float oacc[8][4];
#pragma unroll
    for (int j = 0; j < 8; j++)
#pragma unroll
        for (int r = 0; r < 4; r++) oacc[j][r] = 0.0f;
    float m0r = -1e30f, m1r = -1e30f, l0r = 0.0f, l1r = 0.0f;

    for (int kt = 0; kt <= qTile; kt++) {
        const int k0 = kt * 64;

        // V prefetch (overlaps S-matmul; Vs free per loop-end sync)
#pragma unroll
        for (int it = 0; it < 8; it++) {
            const int idx = tid + it * 128;
            const int r = idx >> 4, c4 = (idx & 15) << 2;
            cp_async16(&Vs[r * 72 + c4], &Vg[(size_t)(k0 + r) * HDIM + c4]);
        }
        CP_COMMIT();

        // K transpose load: [key][hd] -> Kt[hd][key] (stride 72)
#pragma unroll
        for (int it = 0; it < 8; it++) {
            const int idx = tid + it * 128;
            const int r = idx & 63, c4 = (idx >> 6) << 2;
            float4 v = *(const float4*)&Kg[(size_t)(k0 + r) * HDIM + c4];
            Kt[(c4 + 0) * 72 + r] = v.x;
            Kt[(c4 + 1) * 72 + r] = v.y;
            Kt[(c4 + 2) * 72 + r] = v.z;
            Kt[(c4 + 3) * 72 + r] = v.w;
        }
        __syncthreads();   // Kt ready

        // S = Q @ K^T
        float sacc[8][4];
#pragma unroll
        for (int j = 0; j < 8; j++)
#pragma unroll
            for (int r = 0; r < 4; r++) sacc[j][r] = 0.0f;

#pragma unroll
        for (int ks = 0; ks < 8; ks++) {
            const int ko = ks * 8;
            unsigned bf[8][2];
#pragma unroll
            for (int j = 0; j < 8; j++) {
                const int key = j * 8 + (lane >> 2);
                bf[j][0] = __float_as_uint(Kt[(ko + (lane & 3)) * 72 + key]);
                bf[j][1] = __float_as_uint(Kt[(ko + (lane & 3) + 4) * 72 + key]);
            }
#pragma unroll
            for (int j = 0; j < 8; j++) mma_tf32(sacc[j], qf[ks], bf[j]);
        }

        // scale + causal mask (diag tile only)
        const float scl = 0.125f;   // 1/sqrt(64)
        if (kt == qTile) {
            const int r0 = wid * 16 + (lane >> 2);
            const int r1 = r0 + 8;
#pragma unroll
            for (int j = 0; j < 8; j++) {
                const int c = j * 8 + 2 * (lane & 3);
                sacc[j][0] = (c     > r0) ? -1e30f : sacc[j][0] * scl;
                sacc[j][1] = (c + 1 > r0) ? -1e30f : sacc[j][1] * scl;
                sacc[j][2] = (c     > r1) ? -1e30f : sacc[j][2] * scl;
                sacc[j][3] = (c + 1 > r1) ? -1e30f : sacc[j][3] * scl;
            }
        } else {
#pragma unroll
            for (int j = 0; j < 8; j++)
#pragma unroll
                for (int r = 0; r < 4; r++) sacc[j][r] *= scl;
        }

        // online softmax (rows owned by 4-lane groups)
        float rm0 = -1e30f, rm1 = -1e30f;
#pragma unroll
        for (int j = 0; j < 8; j++) {
            rm0 = fmaxf(rm0, fmaxf(sacc[j][0], sacc[j][1]));
            rm1 = fmaxf(rm1, fmaxf(sacc[j][2], sacc[j][3]));
        }
#pragma unroll
        for (int s = 1; s < 4; s <<= 1) {
            rm0 = fmaxf(rm0, __shfl_xor_sync(0xffffffffu, rm0, s));
            rm1 = fmaxf(rm1, __shfl_xor_sync(0xffffffffu, rm1, s));
        }
        const float mn0 = fmaxf(m0r, rm0);
        const float mn1 = fmaxf(m1r, rm1);
        const float al0 = __expf(m0r - mn0);
        const float al1 = __expf(m1r - mn1);
        float rs0 = 0.0f, rs1 = 0.0f;
#pragma unroll
        for (int j = 0; j < 8; j++) {
            sacc[j][0] = __expf(sacc[j][0] - mn0);
            sacc[j][1] = __expf(sacc[j][1] - mn0);
            sacc[j][2] = __expf(sacc[j][2] - mn1);
            sacc[j][3] = __expf(sacc[j][3] - mn1);
            rs0 += sacc[j][0] + sacc[j][1];
            rs1 += sacc[j][2] + sacc[j][3];
        }
#pragma unroll
        for (int s = 1; s < 4; s <<= 1) {
            rs0 += __shfl_xor_sync(0xffffffffu, rs0, s);
            rs1 += __shfl_xor_sync(0xffffffffu, rs1, s);
        }
        l0r = l0r * al0 + rs0;
        l1r = l1r * al1 + rs1;
        m0r = mn0;
        m1r = mn1;
#pragma unroll
        for (int j = 0; j < 8; j++) {
            oacc[j][0] *= al0;
            oacc[j][1] *= al0;
            oacc[j][2] *= al1;
            oacc[j][3] *= al1;
            // round P to tf32 once (after the l-sum, matching prior numerics)
            sacc[j][0] = f2tff(sacc[j][0]);
            sacc[j][1] = f2tff(sacc[j][1]);
            sacc[j][2] = f2tff(sacc[j][2]);
            sacc[j][3] = f2tff(sacc[j][3]);
        }

        CP_WAIT(0);
        __syncthreads();   // Vs ready (cross-thread visibility)

        // O += P @ V : P C-frag -> A-frag via shuffles
        const int t  = lane & 3;
        const int sl = (lane & ~3) | (t >> 1);
        const int sh = sl + 2;
        const bool odd = t & 1;
#pragma unroll
        for (int ks = 0; ks < 8; ks++) {
            const int ko = ks * 8;
            float p00 = __shfl_sync(0xffffffffu, sacc[ks][0], sl);
            float p01 = __shfl_sync(0xffffffffu, sacc[ks][1], sl);
            float p10 = __shfl_sync(0xffffffffu, sacc[ks][2], sl);
            float p11 = __shfl_sync(0xffffffffu, sacc[ks][3], sl);
            float r00 = __shfl_sync(0xffffffffu, sacc[ks][0], sh);
            float r01 = __shfl_sync(0xffffffffu, sacc[ks][1], sh);
            float r10 = __shfl_sync(0xffffffffu, sacc[ks][2], sh);
            float r11 = __shfl_sync(0xffffffffu, sacc[ks][3], sh);
            unsigned af[4];
            af[0] = __float_as_uint(odd ? p01 : p00);   // P[g   ][ko+t]
            af[1] = __float_as_uint(odd ? p11 : p10);   // P[g+8 ][ko+t]
            af[2] = __float_as_uint(odd ? r01 : r00);   // P[g   ][ko+t+4]
            af[3] = __float_as_uint(odd ? r11 : r10);   // P[g+8 ][ko+t+4]
            unsigned bf[8][2];
#pragma unroll
            for (int j = 0; j < 8; j++) {
                const int n = j * 8 + (lane >> 2);
                bf[j][0] = __float_as_uint(Vs[(ko + (lane & 3)) * 72 + n]);
                bf[j][1] = __float_as_uint(Vs[(ko + (lane & 3) + 4) * 72 + n]);
            }
#pragma unroll
            for (int j = 0; j < 8; j++) mma_tf32(oacc[j], af, bf[j]);
        }
        __syncthreads();   // Kt/Vs readers done before next-iter overwrite
    }

    // write merged-head output [B,T,D], tf32-rounded (proj consumes as tf32)
    const int b = bh >> 4;
    const int h = bh & 15;
    const float il0 = 1.0f / l0r;
    const float il1 = 1.0f / l1r;
    const int t0 = q0 + wid * 16 + (lane >> 2);
    float* base0 = g_attn + ((size_t)(b * SEQ + t0)) * DMODEL + h * HDIM;
    float* base1 = g_attn + ((size_t)(b * SEQ + t0 + 8)) * DMODEL + h * HDIM;
#pragma unroll
    for (int j = 0; j < 8; j++) {
        const int c = j * 8 + 2 * (lane & 3);
        *(float2*)&base0[c] = make_float2(f2tff(oacc[j][0] * il0), f2tff(oacc[j][1] * il0));
        *(float2*)&base1[c] = make_float2(f2tff(oacc[j][2] * il1), f2tff(oacc[j][3] * il1));
    }
}

// ---------------------------------------------------------------------------
// kernel_launch
// inputs: 0 hidden_states [B,T,D] f32, 1 w_attn [D,3D], 2 b_attn [3D],
//         3 w_proj [D,D], 4 b_proj [D]; output [B,T,D] f32
// ---------------------------------------------------------------------------
extern "C" void kernel_launch(void* const* d_in, const int* in_sizes, int n_in,
                              void* d_out, int out_size)
{
    const float* hidden = (const float*)d_in[0];
    const float* w_attn = (const float*)d_in[1];
    const float* b_attn = (const float*)d_in[2];
    const float* w_proj = (const float*)d_in[3];
    const float* b_proj = (const float*)d_in[4];
    float* out = (float*)d_out;

    // 0) prepass: round inputs/weights to tf32 once
    {
        float* d_hid;  cudaGetSymbolAddress((void**)&d_hid,  g_hid);
        float* d_wq;   cudaGetSymbolAddress((void**)&d_wq,   g_wqkv);
        float* d_wp;   cudaGetSymbolAddress((void**)&d_wp,   g_wp);
        round_tf32_kernel<<<(MROWS * DMODEL / 4 + 255) / 256, 256>>>(
            hidden, d_hid, MROWS * DMODEL / 4);
        round_tf32_kernel<<<(DMODEL * 3 * DMODEL / 4 + 255) / 256, 256>>>(
            w_attn, d_wq, DMODEL * 3 * DMODEL / 4);
        round_tf32_kernel<<<(DMODEL * DMODEL / 4 + 255) / 256, 256>>>(
            w_proj, d_wp, DMODEL * DMODEL / 4);
    }

    // 1) QKV GEMM + bias + head split (zero-cvt mainloop)
    gemm_tf32<0><<<dim3(3 * DMODEL / 128, MROWS / 128), 256>>>(
        b_attn, nullptr, DMODEL, 3 * DMODEL);

    // 2) causal flash attention
    flash_tc<<<dim3(SEQ / 64, BATCH * NHEAD), 128>>>();

    // 3) output projection + bias
    gemm_tf32<1><<<dim3(DMODEL / 128, MROWS / 128), 256>>>(
        b_proj, out, DMODEL, DMODEL);
}

// round 6
// speedup vs baseline: 6.3010x; 2.0217x over previous
#include <cuda_runtime.h>
#include <cuda_fp16.h>

// Problem constants
#define BATCH 4
#define SEQ   2048
#define DMODEL 1024
#define NHEAD 16
#define HDIM  64
#define MROWS (BATCH * SEQ)          // 8192

// Scratch (device globals; allocation-free). All fp16.
__device__ __half g_qh[BATCH * NHEAD * SEQ * HDIM];     // [B,H,T,HD]
__device__ __half g_kh[BATCH * NHEAD * SEQ * HDIM];     // [B,H,T,HD]
__device__ __half g_vth[BATCH * NHEAD * HDIM * SEQ];    // [B,H,HD,T] (transposed)
__device__ __half g_attnh[MROWS * DMODEL];              // [B,T,D]
__device__ __half g_hidh[MROWS * DMODEL];               // fp16 hidden
__device__ __half g_wqkvt[3 * DMODEL * DMODEL];         // w_attn^T [3D][D]
__device__ __half g_wpt[DMODEL * DMODEL];               // w_proj^T [D][D]

// ---------------------------------------------------------------------------
// helpers
// ---------------------------------------------------------------------------
__device__ __forceinline__ void mma_f16(float* d, const unsigned* a, const unsigned* b) {
    asm volatile(
        "mma.sync.aligned.m16n8k16.row.col.f32.f16.f16.f32 "
        "{%0,%1,%2,%3},{%4,%5,%6,%7},{%8,%9},{%0,%1,%2,%3};\n"
        : "+f"(d[0]), "+f"(d[1]), "+f"(d[2]), "+f"(d[3])
        : "r"(a[0]), "r"(a[1]), "r"(a[2]), "r"(a[3]), "r"(b[0]), "r"(b[1]));
}

__device__ __forceinline__ unsigned pack2h(float a, float b) {
    __half2 h = __floats2half2_rn(a, b);
    return *(unsigned*)&h;
}

__device__ __forceinline__ void cp_async16(void* smem, const void* g) {
    unsigned s = (unsigned)__cvta_generic_to_shared(smem);
    asm volatile("cp.async.cg.shared.global [%0], [%1], 16;\n" :: "r"(s), "l"(g));
}
#define CP_COMMIT() asm volatile("cp.async.commit_group;\n" ::: "memory")
#define CP_WAIT(n)  asm volatile("cp.async.wait_group %0;\n" :: "n"(n) : "memory")

// ---------------------------------------------------------------------------
// Prepass 1: fp32 -> fp16 (vectorized)
// ---------------------------------------------------------------------------
__global__ __launch_bounds__(256) void f32_to_f16_kernel(
    const float* __restrict__ src, __half* __restrict__ dst, int n4)
{
    int i = blockIdx.x * blockDim.x + threadIdx.x;
    if (i < n4) {
        float4 v = ((const float4*)src)[i];
        __half2 h0 = __floats2half2_rn(v.x, v.y);
        __half2 h1 = __floats2half2_rn(v.z, v.w);
        ((uint2*)dst)[i] = make_uint2(*(unsigned*)&h0, *(unsigned*)&h1);
    }
}

// ---------------------------------------------------------------------------
// Prepass 2: transpose + convert: W [K][N] f32 -> Wt [N][K] f16
// (K, N multiples of 32)
// ---------------------------------------------------------------------------
__global__ void transpose_to_f16_kernel(
    const float* __restrict__ src, __half* __restrict__ dst, int K, int N)
{
    __shared__ float t[32][33];
    int n = blockIdx.x * 32 + threadIdx.x;
    int k = blockIdx.y * 32 + threadIdx.y;
    t[threadIdx.y][threadIdx.x] = src[(size_t)k * N + n];
    __syncthreads();
    int no = blockIdx.x * 32 + threadIdx.y;
    int ko = blockIdx.y * 32 + threadIdx.x;
    dst[(size_t)no * K + ko] = __float2half_rn(t[threadIdx.x][threadIdx.y]);
}

// ---------------------------------------------------------------------------
// FP16 tensor-core GEMM: C[M,N] = A[M,K] @ W[K,N] + bias  (W pre-transposed)
// MODE 0: A = g_hidh, Wt = g_wqkvt, scatter fp16 into g_qh/g_kh/g_vth
// MODE 1: A = g_attnh, Wt = g_wpt, write fp32 C (d_out)
// Block tile 128x128x32, 8 warps (warp tile 32x64), cp.async double buffer.
// smem stride 40 halves (conflict-free frag loads; 80B rows, 16B-aligned).
// ---------------------------------------------------------------------------
template <int MODE>
__global__ __launch_bounds__(256, 2) void gemm_f16(
    const float* __restrict__ bias,
    float* __restrict__ C,
    int Kdim, int Ndim)
{
    __shared__ __half As[2][128 * 40];
    __shared__ __half Bs[2][128 * 40];

    const __half* A  = (MODE == 0) ? g_hidh  : g_attnh;
    const __half* Wt = (MODE == 0) ? g_wqkvt : g_wpt;

    const int m0 = blockIdx.y * 128;
    const int n0 = blockIdx.x * 128;
    const int tid  = threadIdx.x;
    const int lane = tid & 31;
    const int wid  = tid >> 5;
    const int wr = (wid & 3) * 32;   // warp row offset (4 warps in M)
    const int wc = (wid >> 2) * 64;  // warp col offset (2 warps in N)
    const int g  = lane >> 2;
    const int t2 = (lane & 3) * 2;

    float acc[2][8][4];
#pragma unroll
    for (int i = 0; i < 2; i++)
#pragma unroll
        for (int j = 0; j < 8; j++)
#pragma unroll
            for (int r = 0; r < 4; r++) acc[i][j][r] = 0.0f;

    // Tile loaders: 128 rows x 32 halves (64B = 4x16B chunks) each for A and Wt.
#define LOAD_A(KT_, ST_)                                                        \
    _Pragma("unroll")                                                           \
    for (int i_ = 0; i_ < 2; i_++) {                                            \
        int c_ = tid + i_ * 256;                                                \
        int row_ = c_ >> 2, cc_ = (c_ & 3) * 8;                                 \
        cp_async16(&As[ST_][row_ * 40 + cc_],                                   \
                   &A[(size_t)(m0 + row_) * Kdim + (KT_) + cc_]);               \
    }
#define LOAD_B(KT_, ST_)                                                        \
    _Pragma("unroll")                                                           \
    for (int i_ = 0; i_ < 2; i_++) {                                            \
        int c_ = tid + i_ * 256;                                                \
        int row_ = c_ >> 2, cc_ = (c_ & 3) * 8;                                 \
        cp_async16(&Bs[ST_][row_ * 40 + cc_],                                   \
                   &Wt[(size_t)(n0 + row_) * Kdim + (KT_) + cc_]);              \
    }

    LOAD_A(0, 0);
    LOAD_B(0, 0);
    CP_COMMIT();

    const int KT = Kdim >> 5;   // 32-wide k tiles
    int st = 0;
    for (int kt = 0; kt < KT; kt++) {
        if (kt + 1 < KT) {
            LOAD_A((kt + 1) << 5, st ^ 1);
            LOAD_B((kt + 1) << 5, st ^ 1);
            CP_COMMIT();
            CP_WAIT(1);
        } else {
            CP_WAIT(0);
        }
        __syncthreads();

        const __half* as = As[st];
        const __half* bs = Bs[st];
#pragma unroll
        for (int kc = 0; kc < 2; kc++) {
            const int ko = kc * 16;
            unsigned af[2][4], bf[8][2];
#pragma unroll
            for (int i = 0; i < 2; i++) {
                const int r = wr + i * 16 + g;
                const int base = r * 40 + ko + t2;
                af[i][0] = *(const unsigned*)&as[base];          // A[r  ][2t,2t+1]
                af[i][1] = *(const unsigned*)&as[base + 320];    // A[r+8][2t,2t+1]
                af[i][2] = *(const unsigned*)&as[base + 8];      // A[r  ][2t+8,+9]
                af[i][3] = *(const unsigned*)&as[base + 328];    // A[r+8][2t+8,+9]
            }
#pragma unroll
            for (int j = 0; j < 8; j++) {
                const int col = wc + j * 8 + g;
                const int bb = col * 40 + ko + t2;
                bf[j][0] = *(const unsigned*)&bs[bb];            // B[2t,2t+1][col]
                bf[j][1] = *(const unsigned*)&bs[bb + 8];        // B[2t+8,+9][col]
            }
#pragma unroll
            for (int i = 0; i < 2; i++)
#pragma unroll
                for (int j = 0; j < 8; j++) mma_f16(acc[i][j], af[i], bf[j]);
        }
        __syncthreads();
        st ^= 1;
    }

    // epilogue: c0,c1 = (row, 2c),(row, 2c+1); c2,c3 at row+8
#pragma unroll
    for (int i = 0; i < 2; i++) {
#pragma unroll
        for (int rr = 0; rr < 2; rr++) {
            const int row = m0 + wr + i * 16 + g + rr * 8;
#pragma unroll
            for (int j = 0; j < 8; j++) {
                const int col = n0 + wc + j * 8 + t2;
                const float v0 = acc[i][j][rr * 2 + 0] + bias[col];
                const float v1 = acc[i][j][rr * 2 + 1] + bias[col + 1];
                if (MODE == 0) {
                    const int which = col >> 10;       // 0=q,1=k,2=v
                    const int d  = col & 1023;
                    const int h  = d >> 6;
                    const int hd = d & 63;
                    const int b  = row >> 11;
                    const int t  = row & 2047;
                    if (which < 2) {
                        __half* dst = (which == 0) ? g_qh : g_kh;
                        const size_t idx =
                            (((size_t)(b * NHEAD + h)) * SEQ + t) * HDIM + hd;
                        __half2 hv = __floats2half2_rn(v0, v1);
                        *(__half2*)&dst[idx] = hv;
                    } else {
                        // V transposed: [B,H,HD,T]
                        const size_t idx =
                            (((size_t)(b * NHEAD + h)) * HDIM + hd) * SEQ + t;
                        g_vth[idx]       = __float2half_rn(v0);
                        g_vth[idx + SEQ] = __float2half_rn(v1);
                    }
                } else {
                    *(float2*)&C[(size_t)row * Ndim + col] = make_float2(v0, v1);
                }
            }
        }
    }
#undef LOAD_A
#undef LOAD_B
}

// ---------------------------------------------------------------------------
// Causal flash attention, FP16 tensor cores (m16n8k16), fully cp.async.
// Block 128 threads (4 warps), Q tile 64 (16 rows/warp), key tile 64, HD=64.
// K natural [key][hd], V pre-transposed [hd][key]; both double-buffered and
// prefetched one full tile ahead. P C-frag -> A-frag is pure register packing.
// smem: 4 x 64x72 half = 36.9 KB.
// ---------------------------------------------------------------------------
__global__ __launch_bounds__(128, 4) void flash_f16()
{
    __shared__ __half Ks[2][64 * 72];
    __shared__ __half Vts[2][64 * 72];

    const int qTile = blockIdx.x;
    const int bh    = blockIdx.y;

    const __half* Qh  = g_qh  + (size_t)bh * SEQ * HDIM;
    const __half* Kh  = g_kh  + (size_t)bh * SEQ * HDIM;
    const __half* Vth = g_vth + (size_t)bh * HDIM * SEQ;

    const int tid  = threadIdx.x;
    const int lane = tid & 31;
    const int wid  = tid >> 5;
    const int g    = lane >> 2;
    const int t2   = (lane & 3) * 2;
    const int q0   = qTile * 64;
    const int qr   = q0 + wid * 16 + g;

    // preload Q fragments (4 k16-chunks over HD=64)
    unsigned qf[4][4];
#pragma unroll
    for (int kc = 0; kc < 4; kc++) {
        const int ko = kc * 16 + t2;
        qf[kc][0] = *(const unsigned*)&Qh[(size_t)qr * HDIM + ko];
        qf[kc][1] = *(const unsigned*)&Qh[(size_t)(qr + 8) * HDIM + ko];
        qf[kc][2] = *(const unsigned*)&Qh[(size_t)qr * HDIM + ko + 8];
        qf[kc][3] = *(const unsigned*)&Qh[(size_t)(qr + 8) * HDIM + ko + 8];
    }

    float oacc[8][4];
#pragma unroll
    for (int j = 0; j < 8; j++)
#pragma unroll
        for (int r = 0; r < 4; r++) oacc[j][r] = 0.0f;
    float m0r = -1e30f, m1r = -1e30f, l0r = 0.0f, l1r = 0.0f;

    // prologue: load tile 0 (K rows 128B, Vt rows 128B; 8 chunks/thread total)
#pragma unroll
    for (int it = 0; it < 4; it++) {
        const int c = tid + it * 128;
        const int r = c >> 3, cc = (c & 7) * 8;
        cp_async16(&Ks[0][r * 72 + cc], &Kh[(size_t)r * HDIM + cc]);
    }
#pragma unroll
    for (int it = 0; it < 4; it++) {
        const int c = tid + it * 128;
        const int r = c >> 3, cc = (c & 7) * 8;
        cp_async16(&Vts[0][r * 72 + cc], &Vth[(size_t)r * SEQ + cc]);
    }
    CP_COMMIT();

    for (int kt = 0; kt <= qTile; kt++) {
        const int st = kt & 1;
        CP_WAIT(0);
        __syncthreads();   // tile kt resident & visible

        // prefetch tile kt+1 into the other buffer (overlaps all compute below)
        if (kt < qTile) {
            const int kn = (kt + 1) * 64;
#pragma unroll
            for (int it = 0; it < 4; it++) {
                const int c = tid + it * 128;
                const int r = c >> 3, cc = (c & 7) * 8;
                cp_async16(&Ks[st ^ 1][r * 72 + cc],
                           &Kh[(size_t)(kn + r) * HDIM + cc]);
            }
#pragma unroll
            for (int it = 0; it < 4; it++) {
                const int c = tid + it * 128;
                const int r = c >> 3, cc = (c & 7) * 8;
                cp_async16(&Vts[st ^ 1][r * 72 + cc],
                           &Vth[(size_t)r * SEQ + kn + cc]);
            }
            CP_COMMIT();
        }

        // S = Q @ K^T
        float sacc[8][4];
#pragma unroll
        for (int j = 0; j < 8; j++)
#pragma unroll
            for (int r = 0; r < 4; r++) sacc[j][r] = 0.0f;

#pragma unroll
        for (int kc = 0; kc < 4; kc++) {
            const int ko = kc * 16 + t2;
            unsigned bf[8][2];
#pragma unroll
            for (int j = 0; j < 8; j++) {
                const int kb = (j * 8 + g) * 72 + ko;
                bf[j][0] = *(const unsigned*)&Ks[st][kb];
                bf[j][1] = *(const unsigned*)&Ks[st][kb + 8];
            }
#pragma unroll
            for (int j = 0; j < 8; j++) mma_f16(sacc[j], qf[kc], bf[j]);
        }

        // scale + causal mask (diag tile only)
        const float scl = 0.125f;   // 1/sqrt(64)
        if (kt == qTile) {
            const int r0 = wid * 16 + g;
            const int r1 = r0 + 8;
#pragma unroll
            for (int j = 0; j < 8; j++) {
                const int c = j * 8 + t2;
                sacc[j][0] = (c     > r0) ? -1e30f : sacc[j][0] * scl;
                sacc[j][1] = (c + 1 > r0) ? -1e30f : sacc[j][1] * scl;
                sacc[j][2] = (c     > r1) ? -1e30f : sacc[j][2] * scl;
                sacc[j][3] = (c + 1 > r1) ? -1e30f : sacc[j][3] * scl;
            }
        } else {
#pragma unroll
            for (int j = 0; j < 8; j++)
#pragma unroll
                for (int r = 0; r < 4; r++) sacc[j][r] *= scl;
        }

        // online softmax (rows owned by 4-lane groups; xor-reduce over 1,2)
        float rm0 = -1e30f, rm1 = -1e30f;
#pragma unroll
        for (int j = 0; j < 8; j++) {
            rm0 = fmaxf(rm0, fmaxf(sacc[j][0], sacc[j][1]));
            rm1 = fmaxf(rm1, fmaxf(sacc[j][2], sacc[j][3]));
        }
#pragma unroll
        for (int s = 1; s < 4; s <<= 1) {
            rm0 = fmaxf(rm0, __shfl_xor_sync(0xffffffffu, rm0, s));
            rm1 = fmaxf(rm1, __shfl_xor_sync(0xffffffffu, rm1, s));
        }
        const float mn0 = fmaxf(m0r, rm0);
        const float mn1 = fmaxf(m1r, rm1);
        const float al0 = __expf(m0r - mn0);
        const float al1 = __expf(m1r - mn1);
        float rs0 = 0.0f, rs1 = 0.0f;
#pragma unroll
        for (int j = 0; j < 8; j++) {
            sacc[j][0] = __expf(sacc[j][0] - mn0);
            sacc[j][1] = __expf(sacc[j][1] - mn0);
            sacc[j][2] = __expf(sacc[j][2] - mn1);
            sacc[j][3] = __expf(sacc[j][3] - mn1);
            rs0 += sacc[j][0] + sacc[j][1];
            rs1 += sacc[j][2] + sacc[j][3];
        }
#pragma unroll
        for (int s = 1; s < 4; s <<= 1) {
            rs0 += __shfl_xor_sync(0xffffffffu, rs0, s);
            rs1 += __shfl_xor_sync(0xffffffffu, rs1, s);
        }
        l0r = l0r * al0 + rs0;
        l1r = l1r * al1 + rs1;
        m0r = mn0;
        m1r = mn1;
#pragma unroll
        for (int j = 0; j < 8; j++) {
            oacc[j][0] *= al0;
            oacc[j][1] *= al0;
            oacc[j][2] *= al1;
            oacc[j][3] *= al1;
        }

        // O += P @ V : A-frag = register-packed S C-frags (no smem, no shfl)
#pragma unroll
        for (int kc = 0; kc < 4; kc++) {
            unsigned af[4];
            af[0] = pack2h(sacc[2 * kc][0],     sacc[2 * kc][1]);
            af[1] = pack2h(sacc[2 * kc][2],     sacc[2 * kc][3]);
            af[2] = pack2h(sacc[2 * kc + 1][0], sacc[2 * kc + 1][1]);
            af[3] = pack2h(sacc[2 * kc + 1][2], sacc[2 * kc + 1][3]);
            const int ko = kc * 16 + t2;
            unsigned bf[8][2];
#pragma unroll
            for (int j = 0; j < 8; j++) {
                const int vb = (j * 8 + g) * 72 + ko;
                bf[j][0] = *(const unsigned*)&Vts[st][vb];
                bf[j][1] = *(const unsigned*)&Vts[st][vb + 8];
            }
#pragma unroll
            for (int j = 0; j < 8; j++) mma_f16(oacc[j], af, bf[j]);
        }
        __syncthreads();   // all warps done with buffer st before it is refilled
    }

    // write merged-head output [B,T,D] as fp16 (proj consumes fp16)
    const int b = bh >> 4;
    const int h = bh & 15;
    const float il0 = 1.0f / l0r;
    const float il1 = 1.0f / l1r;
    const int t0 = q0 + wid * 16 + g;
    __half* base0 = g_attnh + ((size_t)(b * SEQ + t0)) * DMODEL + h * HDIM;
    __half* base1 = g_attnh + ((size_t)(b * SEQ + t0 + 8)) * DMODEL + h * HDIM;
#pragma unroll
    for (int j = 0; j < 8; j++) {
        const int c = j * 8 + t2;
        __half2 h0 = __floats2half2_rn(oacc[j][0] * il0, oacc[j][1] * il0);
        __half2 h1 = __floats2half2_rn(oacc[j][2] * il1, oacc[j][3] * il1);
        *(__half2*)&base0[c] = h0;
        *(__half2*)&base1[c] = h1;
    }
}

// ---------------------------------------------------------------------------
// kernel_launch
// inputs: 0 hidden_states [B,T,D] f32, 1 w_attn [D,3D], 2 b_attn [3D],
//         3 w_proj [D,D], 4 b_proj [D]; output [B,T,D] f32
// ---------------------------------------------------------------------------
extern "C" void kernel_launch(void* const* d_in, const int* in_sizes, int n_in,
                              void* d_out, int out_size)
{
    const float* hidden = (const float*)d_in[0];
    const float* w_attn = (const float*)d_in[1];
    const float* b_attn = (const float*)d_in[2];
    const float* w_proj = (const float*)d_in[3];
    const float* b_proj = (const float*)d_in[4];
    float* out = (float*)d_out;

    // 0) prepass: fp16 convert + weight transpose
    {
        __half* d_hid; cudaGetSymbolAddress((void**)&d_hid, g_hidh);
        __half* d_wq;  cudaGetSymbolAddress((void**)&d_wq,  g_wqkvt);
        __half* d_wp;  cudaGetSymbolAddress((void**)&d_wp,  g_wpt);
        f32_to_f16_kernel<<<(MROWS * DMODEL / 4 + 255) / 256, 256>>>(
            hidden, d_hid, MROWS * DMODEL / 4);
        transpose_to_f16_kernel<<<dim3(3 * DMODEL / 32, DMODEL / 32), dim3(32, 32)>>>(
            w_attn, d_wq, DMODEL, 3 * DMODEL);
        transpose_to_f16_kernel<<<dim3(DMODEL / 32, DMODEL / 32), dim3(32, 32)>>>(
            w_proj, d_wp, DMODEL, DMODEL);
    }

    // 1) QKV GEMM + bias + head split (fp16 m16n8k16)
    gemm_f16<0><<<dim3(3 * DMODEL / 128, MROWS / 128), 256>>>(
        b_attn, nullptr, DMODEL, 3 * DMODEL);

    // 2) causal flash attention (fp16, double-buffered cp.async K/V)
    flash_f16<<<dim3(SEQ / 64, BATCH * NHEAD), 128>>>();

    // 3) output projection + bias (fp16 -> fp32 out)
    gemm_f16<1><<<dim3(DMODEL / 128, MROWS / 128), 256>>>(
        b_proj, out, DMODEL, DMODEL);
}

// round 8
// speedup vs baseline: 7.8613x; 1.2476x over previous
#include <cuda_runtime.h>
#include <cuda_fp16.h>
#include <cstdint>

// Problem constants
#define BATCH 4
#define SEQ   2048
#define DMODEL 1024
#define NHEAD 16
#define HDIM  64
#define MROWS (BATCH * SEQ)          // 8192

// Scratch (device globals; allocation-free). All fp16.
__device__ __half g_qh[BATCH * NHEAD * SEQ * HDIM];     // [B,H,T,HD]
__device__ __half g_kh[BATCH * NHEAD * SEQ * HDIM];     // [B,H,T,HD]
__device__ __half g_vth[BATCH * NHEAD * HDIM * SEQ];    // [B,H,HD,T] (transposed)
__device__ __half g_attnh[MROWS * DMODEL];              // [B,T,D]
__device__ __half g_hidh[MROWS * DMODEL];               // fp16 hidden
__device__ __half g_wqkvt[3 * DMODEL * DMODEL];         // w_attn^T [3D][D]
__device__ __half g_wpt[DMODEL * DMODEL];               // w_proj^T [D][D]

// ---------------------------------------------------------------------------
// helpers
// ---------------------------------------------------------------------------
__device__ __forceinline__ unsigned smem_u32(const void* p) {
    return (unsigned)__cvta_generic_to_shared(p);
}
__device__ __forceinline__ void cp_async16(unsigned s, const void* g) {
    asm volatile("cp.async.cg.shared.global [%0], [%1], 16;\n" :: "r"(s), "l"(g));
}
#define CP_COMMIT() asm volatile("cp.async.commit_group;\n" ::: "memory")
#define CP_WAIT(n)  asm volatile("cp.async.wait_group %0;\n" :: "n"(n) : "memory")

__device__ __forceinline__ unsigned pack2h(float a, float b) {
    __half2 h = __floats2half2_rn(a, b);
    return *(unsigned*)&h;
}
__device__ __forceinline__ void mma_f16s(float* d, const unsigned* a, const unsigned* b) {
    asm volatile(
        "mma.sync.aligned.m16n8k16.row.col.f32.f16.f16.f32 "
        "{%0,%1,%2,%3},{%4,%5,%6,%7},{%8,%9},{%0,%1,%2,%3};\n"
        : "+f"(d[0]), "+f"(d[1]), "+f"(d[2]), "+f"(d[3])
        : "r"(a[0]), "r"(a[1]), "r"(a[2]), "r"(a[3]), "r"(b[0]), "r"(b[1]));
}
__device__ __forceinline__ void ldm_x4(unsigned* r, unsigned addr) {
    asm volatile(
        "ldmatrix.sync.aligned.m8n8.x4.shared.b16 {%0,%1,%2,%3}, [%4];"
        : "=r"(r[0]), "=r"(r[1]), "=r"(r[2]), "=r"(r[3]) : "r"(addr));
}

// ---------------------------------------------------------------------------
// Prepass 1: fp32 -> fp16 (vectorized)
// ---------------------------------------------------------------------------
__global__ __launch_bounds__(256) void f32_to_f16_kernel(
    const float* __restrict__ src, __half* __restrict__ dst, int n4)
{
    int i = blockIdx.x * blockDim.x + threadIdx.x;
    if (i < n4) {
        float4 v = ((const float4*)src)[i];
        __half2 h0 = __floats2half2_rn(v.x, v.y);
        __half2 h1 = __floats2half2_rn(v.z, v.w);
        ((uint2*)dst)[i] = make_uint2(*(unsigned*)&h0, *(unsigned*)&h1);
    }
}

// ---------------------------------------------------------------------------
// Prepass 2: transpose + convert: W [K][N] f32 -> Wt [N][K] f16
// ---------------------------------------------------------------------------
__global__ void transpose_to_f16_kernel(
    const float* __restrict__ src, __half* __restrict__ dst, int K, int N)
{
    __shared__ float t[32][33];
    int n = blockIdx.x * 32 + threadIdx.x;
    int k = blockIdx.y * 32 + threadIdx.y;
    t[threadIdx.y][threadIdx.x] = src[(size_t)k * N + n];
    __syncthreads();
    int no = blockIdx.x * 32 + threadIdx.y;
    int ko = blockIdx.y * 32 + threadIdx.x;
    dst[(size_t)no * K + ko] = __float2half_rn(t[threadIdx.x][threadIdx.y]);
}

// ---------------------------------------------------------------------------
// FP16 mma.sync GEMM: C[M,N] = A[M,K] @ W[K,N] + bias  (Wt pre-transposed [N][K])
// Block tile 128x128, BK=64, 8 warps (warp tile 32x64), 3-stage cp.async.
// smem rows: 64 halves = 128B, XOR-swizzled (chunk ^= row&7); ldmatrix feeds.
// MODE 0: scatter fp16 into g_qh/g_kh/g_vth (+bias). MODE 1: fp32 C (+bias).
// Dynamic smem: 3 stages x (16KB A + 16KB B) = 96KB.
// ---------------------------------------------------------------------------
template <int MODE>
__global__ __launch_bounds__(256, 2) void gemm_f16(
    const float* __restrict__ bias,
    float* __restrict__ C,
    int Kdim, int Ndim)
{
    extern __shared__ __align__(128) unsigned char dsm_raw[];
    unsigned char* dsm =
        (unsigned char*)(((uintptr_t)dsm_raw + 127) & ~(uintptr_t)127);
    unsigned sA[3], sB[3];
#pragma unroll
    for (int s = 0; s < 3; s++) {
        sA[s] = smem_u32(dsm) + s * 16384;
        sB[s] = smem_u32(dsm) + 49152 + s * 16384;
    }

    const __half* A  = (MODE == 0) ? g_hidh  : g_attnh;
    const __half* Wt = (MODE == 0) ? g_wqkvt : g_wpt;

    const int m0 = blockIdx.y * 128;
    const int n0 = blockIdx.x * 128;
    const int tid  = threadIdx.x;
    const int lane = tid & 31;
    const int wid  = tid >> 5;
    const int wr = (wid & 3) * 32;   // warp row offset (4 warps in M)
    const int wc = (wid >> 2) * 64;  // warp col offset (2 warps in N)
    const int g  = lane >> 2;
    const int t2 = (lane & 3) * 2;

    // ldmatrix lane roles
    const int rA  = lane & 15;       // A: row within 16-row pair
    const int cA  = lane >> 4;       // A: k-chunk select (0/1)
    const int selB = lane >> 3;      // B: 0..3
    const int rBo  = ((selB >> 1) << 3) + (lane & 7);
    const int cB   = selB & 1;

    float acc[2][8][4];
#pragma unroll
    for (int i = 0; i < 2; i++)
#pragma unroll
        for (int j = 0; j < 8; j++)
#pragma unroll
            for (int r = 0; r < 4; r++) acc[i][j][r] = 0.0f;

    // Loader: A/B tiles 128 rows x 8 swizzled 16B chunks; 4 chunks each/thread.
#define LOAD_TILE(KT_, ST_)                                                     \
    _Pragma("unroll")                                                           \
    for (int i_ = 0; i_ < 4; i_++) {                                            \
        const int c_ = tid + i_ * 256;                                          \
        const int row_ = c_ >> 3, ch_ = c_ & 7;                                 \
        const unsigned ph_ = row_ * 128 + (((ch_) ^ (row_ & 7)) << 4);          \
        cp_async16(sA[ST_] + ph_, &A[(size_t)(m0 + row_) * Kdim + (KT_) + ch_ * 8]); \
        cp_async16(sB[ST_] + ph_, &Wt[(size_t)(n0 + row_) * Kdim + (KT_) + ch_ * 8]); \
    }

    const int KT = Kdim >> 6;   // 64-wide k tiles
    LOAD_TILE(0, 0);
    CP_COMMIT();
    LOAD_TILE(64, 1);
    CP_COMMIT();

    for (int kt = 0; kt < KT; kt++) {
        const int st = kt % 3;
        if (kt + 1 < KT) { CP_WAIT(1); } else { CP_WAIT(0); }
        __syncthreads();   // tile kt visible; prior compute on buf (kt+2)%3 done

        if (kt + 2 < KT) {
            LOAD_TILE((kt + 2) << 6, (kt + 2) % 3);
            CP_COMMIT();
        }

        const unsigned aB = sA[st], bB = sB[st];
#pragma unroll
        for (int kc = 0; kc < 4; kc++) {
            unsigned af[2][4], bf[8][2];
#pragma unroll
            for (int i = 0; i < 2; i++) {
                const int row = wr + i * 16 + rA;
                const unsigned ph =
                    row * 128 + ((((kc << 1) | cA) ^ (row & 7)) << 4);
                ldm_x4(af[i], aB + ph);
            }
#pragma unroll
            for (int jj = 0; jj < 4; jj++) {
                const int row = wc + jj * 16 + rBo;
                const unsigned ph =
                    row * 128 + ((((kc << 1) | cB) ^ (row & 7)) << 4);
                unsigned q[4];
                ldm_x4(q, bB + ph);
                bf[2 * jj][0]     = q[0];
                bf[2 * jj][1]     = q[1];
                bf[2 * jj + 1][0] = q[2];
                bf[2 * jj + 1][1] = q[3];
            }
#pragma unroll
            for (int i = 0; i < 2; i++)
#pragma unroll
                for (int j = 0; j < 8; j++) mma_f16s(acc[i][j], af[i], bf[j]);
        }
    }

    // epilogue: c0,c1 = (row, 2c),(row, 2c+1); c2,c3 at row+8
#pragma unroll
    for (int i = 0; i < 2; i++) {
#pragma unroll
        for (int rr = 0; rr < 2; rr++) {
            const int row = m0 + wr + i * 16 + g + rr * 8;
#pragma unroll
            for (int j = 0; j < 8; j++) {
                const int col = n0 + wc + j * 8 + t2;
                const float v0 = acc[i][j][rr * 2 + 0] + bias[col];
                const float v1 = acc[i][j][rr * 2 + 1] + bias[col + 1];
                if (MODE == 0) {
                    const int which = col >> 10;       // 0=q,1=k,2=v
                    const int d  = col & 1023;
                    const int h  = d >> 6;
                    const int hd = d & 63;
                    const int b  = row >> 11;
                    const int t  = row & 2047;
                    if (which < 2) {
                        __half* dst = (which == 0) ? g_qh : g_kh;
                        const size_t idx =
                            (((size_t)(b * NHEAD + h)) * SEQ + t) * HDIM + hd;
                        __half2 hv = __floats2half2_rn(v0, v1);
                        *(__half2*)&dst[idx] = hv;
                    } else {
                        const size_t idx =
                            (((size_t)(b * NHEAD + h)) * HDIM + hd) * SEQ + t;
                        g_vth[idx]       = __float2half_rn(v0);
                        g_vth[idx + SEQ] = __float2half_rn(v1);
                    }
                } else {
                    *(float2*)&C[(size_t)row * Ndim + col] = make_float2(v0, v1);
                }
            }
        }
    }
#undef LOAD_TILE
}

// ---------------------------------------------------------------------------
// Causal flash attention, FP16 mma.sync, ldmatrix operand feeds.
// Block 128 threads (4 warps), Q tile 64, key tile 64, HD=64.
// K [key][hd] and V^T [hd][key] tiles: 64 rows x 128B, XOR-swizzled,
// double-buffered cp.async, prefetch distance 1.
// ---------------------------------------------------------------------------
__global__ __launch_bounds__(128, 4) void flash_f16()
{
    __shared__ __align__(128) __half Ks[2][64 * 64];
    __shared__ __align__(128) __half Vts[2][64 * 64];

    const int qTile = blockIdx.x;
    const int bh    = blockIdx.y;

    const __half* Qh  = g_qh  + (size_t)bh * SEQ * HDIM;
    const __half* Kh  = g_kh  + (size_t)bh * SEQ * HDIM;
    const __half* Vth = g_vth + (size_t)bh * HDIM * SEQ;

    const int tid  = threadIdx.x;
    const int lane = tid & 31;
    const int wid  = tid >> 5;
    const int g    = lane >> 2;
    const int t2   = (lane & 3) * 2;
    const int q0   = qTile * 64;
    const int qr   = q0 + wid * 16 + g;

    const int selB = lane >> 3;
    const int rBo  = ((selB >> 1) << 3) + (lane & 7);
    const int cB   = selB & 1;

    const unsigned ksB[2] = { smem_u32(Ks[0]),  smem_u32(Ks[1]) };
    const unsigned vsB[2] = { smem_u32(Vts[0]), smem_u32(Vts[1]) };

    // preload Q fragments (4 k16-chunks over HD=64)
    unsigned qf[4][4];
#pragma unroll
    for (int kc = 0; kc < 4; kc++) {
        const int ko = kc * 16 + t2;
        qf[kc][0] = *(const unsigned*)&Qh[(size_t)qr * HDIM + ko];
        qf[kc][1] = *(const unsigned*)&Qh[(size_t)(qr + 8) * HDIM + ko];
        qf[kc][2] = *(const unsigned*)&Qh[(size_t)qr * HDIM + ko + 8];
        qf[kc][3] = *(const unsigned*)&Qh[(size_t)(qr + 8) * HDIM + ko + 8];
    }

    float oacc[8][4];
#pragma unroll
    for (int j = 0; j < 8; j++)
#pragma unroll
        for (int r = 0; r < 4; r++) oacc[j][r] = 0.0f;
    float m0r = -1e30f, m1r = -1e30f, l0r = 0.0f, l1r = 0.0f;

    // loader: 64 rows x 8 swizzled chunks each; 4 chunks/thread per tile
#define LOAD_KV(K0_, ST_)                                                       \
    _Pragma("unroll")                                                           \
    for (int i_ = 0; i_ < 4; i_++) {                                            \
        const int c_ = tid + i_ * 128;                                          \
        const int r_ = c_ >> 3, ch_ = c_ & 7;                                   \
        const unsigned ph_ = r_ * 128 + (((ch_) ^ (r_ & 7)) << 4);              \
        cp_async16(ksB[ST_] + ph_, &Kh[(size_t)((K0_) + r_) * HDIM + ch_ * 8]); \
        cp_async16(vsB[ST_] + ph_, &Vth[(size_t)r_ * SEQ + (K0_) + ch_ * 8]);   \
    }

    LOAD_KV(0, 0);
    CP_COMMIT();

    for (int kt = 0; kt <= qTile; kt++) {
        const int st = kt & 1;
        CP_WAIT(0);
        __syncthreads();   // tile kt resident & visible

        if (kt < qTile) {
            LOAD_KV((kt + 1) * 64, st ^ 1);
            CP_COMMIT();
        }

        // S = Q @ K^T
        float sacc[8][4];
#pragma unroll
        for (int j = 0; j < 8; j++)
#pragma unroll
            for (int r = 0; r < 4; r++) sacc[j][r] = 0.0f;

#pragma unroll
        for (int kc = 0; kc < 4; kc++) {
            unsigned bf[8][2];
#pragma unroll
            for (int jj = 0; jj < 4; jj++) {
                const int row = jj * 16 + rBo;
                const unsigned ph =
                    row * 128 + ((((kc << 1) | cB) ^ (row & 7)) << 4);
                unsigned q[4];
                ldm_x4(q, ksB[st] + ph);
                bf[2 * jj][0]     = q[0];
                bf[2 * jj][1]     = q[1];
                bf[2 * jj + 1][0] = q[2];
                bf[2 * jj + 1][1] = q[3];
            }
#pragma unroll
            for (int j = 0; j < 8; j++) mma_f16s(sacc[j], qf[kc], bf[j]);
        }

        // scale + causal mask (diag tile only)
        const float scl = 0.125f;   // 1/sqrt(64)
        if (kt == qTile) {
            const int r0 = wid * 16 + g;
            const int r1 = r0 + 8;
#pragma unroll
            for (int j = 0; j < 8; j++) {
                const int c = j * 8 + t2;
                sacc[j][0] = (c     > r0) ? -1e30f : sacc[j][0] * scl;
                sacc[j][1] = (c + 1 > r0) ? -1e30f : sacc[j][1] * scl;
                sacc[j][2] = (c     > r1) ? -1e30f : sacc[j][2] * scl;
                sacc[j][3] = (c + 1 > r1) ? -1e30f : sacc[j][3] * scl;
            }
        } else {
#pragma unroll
            for (int j = 0; j < 8; j++)
#pragma unroll
                for (int r = 0; r < 4; r++) sacc[j][r] *= scl;
        }

        // online softmax (rows owned by 4-lane groups; xor-reduce over 1,2)
        float rm0 = -1e30f, rm1 = -1e30f;
#pragma unroll
        for (int j = 0; j < 8; j++) {
            rm0 = fmaxf(rm0, fmaxf(sacc[j][0], sacc[j][1]));
            rm1 = fmaxf(rm1, fmaxf(sacc[j][2], sacc[j][3]));
        }
#pragma unroll
        for (int s = 1; s < 4; s <<= 1) {
            rm0 = fmaxf(rm0, __shfl_xor_sync(0xffffffffu, rm0, s));
            rm1 = fmaxf(rm1, __shfl_xor_sync(0xffffffffu, rm1, s));
        }
        const float mn0 = fmaxf(m0r, rm0);
        const float mn1 = fmaxf(m1r, rm1);
        const float al0 = __expf(m0r - mn0);
        const float al1 = __expf(m1r - mn1);
        float rs0 = 0.0f, rs1 = 0.0f;
#pragma unroll
        for (int j = 0; j < 8; j++) {
            sacc[j][0] = __expf(sacc[j][0] - mn0);
            sacc[j][1] = __expf(sacc[j][1] - mn0);
            sacc[j][2] = __expf(sacc[j][2] - mn1);
            sacc[j][3] = __expf(sacc[j][3] - mn1);
            rs0 += sacc[j][0] + sacc[j][1];
            rs1 += sacc[j][2] + sacc[j][3];
        }
#pragma unroll
        for (int s = 1; s < 4; s <<= 1) {
            rs0 += __shfl_xor_sync(0xffffffffu, rs0, s);
            rs1 += __shfl_xor_sync(0xffffffffu, rs1, s);
        }
        l0r = l0r * al0 + rs0;
        l1r = l1r * al1 + rs1;
        m0r = mn0;
        m1r = mn1;
#pragma unroll
        for (int j = 0; j < 8; j++) {
            oacc[j][0] *= al0;
            oacc[j][1] *= al0;
            oacc[j][2] *= al1;
            oacc[j][3] *= al1;
        }

        // O += P @ V : A-frag = register-packed S C-frags
#pragma unroll
        for (int kc = 0; kc < 4; kc++) {
            unsigned af[4];
            af[0] = pack2h(sacc[2 * kc][0],     sacc[2 * kc][1]);
            af[1] = pack2h(sacc[2 * kc][2],     sacc[2 * kc][3]);
            af[2] = pack2h(sacc[2 * kc + 1][0], sacc[2 * kc + 1][1]);
            af[3] = pack2h(sacc[2 * kc + 1][2], sacc[2 * kc + 1][3]);
            unsigned bf[8][2];
#pragma unroll
            for (int jj = 0; jj < 4; jj++) {
                const int row = jj * 16 + rBo;
                const unsigned ph =
                    row * 128 + ((((kc << 1) | cB) ^ (row & 7)) << 4);
                unsigned q[4];
                ldm_x4(q, vsB[st] + ph);
                bf[2 * jj][0]     = q[0];
                bf[2 * jj][1]     = q[1];
                bf[2 * jj + 1][0] = q[2];
                bf[2 * jj + 1][1] = q[3];
            }
#pragma unroll
            for (int j = 0; j < 8; j++) mma_f16s(oacc[j], af, bf[j]);
        }
        __syncthreads();   // all warps done with buffer st before refill
    }
#undef LOAD_KV

    // write merged-head output [B,T,D] as fp16 (proj consumes fp16)
    const int b = bh >> 4;
    const int h = bh & 15;
    const float il0 = 1.0f / l0r;
    const float il1 = 1.0f / l1r;
    const int t0 = q0 + wid * 16 + g;
    __half* base0 = g_attnh + ((size_t)(b * SEQ + t0)) * DMODEL + h * HDIM;
    __half* base1 = g_attnh + ((size_t)(b * SEQ + t0 + 8)) * DMODEL + h * HDIM;
#pragma unroll
    for (int j = 0; j < 8; j++) {
        const int c = j * 8 + t2;
        __half2 h0 = __floats2half2_rn(oacc[j][0] * il0, oacc[j][1] * il0);
        __half2 h1 = __floats2half2_rn(oacc[j][2] * il1, oacc[j][3] * il1);
        *(__half2*)&base0[c] = h0;
        *(__half2*)&base1[c] = h1;
    }
}

// ---------------------------------------------------------------------------
// kernel_launch
// inputs: 0 hidden_states [B,T,D] f32, 1 w_attn [D,3D], 2 b_attn [3D],
//         3 w_proj [D,D], 4 b_proj [D]; output [B,T,D] f32
// ---------------------------------------------------------------------------
extern "C" void kernel_launch(void* const* d_in, const int* in_sizes, int n_in,
                              void* d_out, int out_size)
{
    const float* hidden = (const float*)d_in[0];
    const float* w_attn = (const float*)d_in[1];
    const float* b_attn = (const float*)d_in[2];
    const float* w_proj = (const float*)d_in[3];
    const float* b_proj = (const float*)d_in[4];
    float* out = (float*)d_out;

    const int DSM = 3 * 32768 + 128;   // 96KB payload + align slack
    cudaFuncSetAttribute(gemm_f16<0>, cudaFuncAttributeMaxDynamicSharedMemorySize, DSM);
    cudaFuncSetAttribute(gemm_f16<1>, cudaFuncAttributeMaxDynamicSharedMemorySize, DSM);

    // 0) prepass: fp16 convert + weight transpose
    {
        __half* d_hid; cudaGetSymbolAddress((void**)&d_hid, g_hidh);
        __half* d_wq;  cudaGetSymbolAddress((void**)&d_wq,  g_wqkvt);
        __half* d_wp;  cudaGetSymbolAddress((void**)&d_wp,  g_wpt);
        f32_to_f16_kernel<<<(MROWS * DMODEL / 4 + 255) / 256, 256>>>(
            hidden, d_hid, MROWS * DMODEL / 4);
        transpose_to_f16_kernel<<<dim3(3 * DMODEL / 32, DMODEL / 32), dim3(32, 32)>>>(
            w_attn, d_wq, DMODEL, 3 * DMODEL);
        transpose_to_f16_kernel<<<dim3(DMODEL / 32, DMODEL / 32), dim3(32, 32)>>>(
            w_proj, d_wp, DMODEL, DMODEL);
    }

    // 1) QKV GEMM + bias + head split
    gemm_f16<0><<<dim3(3 * DMODEL / 128, MROWS / 128), 256, DSM>>>(
        b_attn, nullptr, DMODEL, 3 * DMODEL);

    // 2) causal flash attention
    flash_f16<<<dim3(SEQ / 64, BATCH * NHEAD), 128>>>();

    // 3) output projection + bias (fp32 out)
    gemm_f16<1><<<dim3(DMODEL / 128, MROWS / 128), 256, DSM>>>(
        b_proj, out, DMODEL, DMODEL);
}

// round 9
// speedup vs baseline: 8.1988x; 1.0429x over previous
#include <cuda_runtime.h>
#include <cuda_fp16.h>
#include <cstdint>

// Problem constants
#define BATCH 4
#define SEQ   2048
#define DMODEL 1024
#define NHEAD 16
#define HDIM  64
#define MROWS (BATCH * SEQ)          // 8192

// Scratch (device globals; allocation-free). All fp16.
__device__ __half g_qh[BATCH * NHEAD * SEQ * HDIM];     // [B,H,T,HD]
__device__ __half g_kh[BATCH * NHEAD * SEQ * HDIM];     // [B,H,T,HD]
__device__ __half g_vth[BATCH * NHEAD * HDIM * SEQ];    // [B,H,HD,T] (transposed)
__device__ __half g_attnh[MROWS * DMODEL];              // [B,T,D]
__device__ __half g_hidh[MROWS * DMODEL];               // fp16 hidden
__device__ __half g_wqkvt[3 * DMODEL * DMODEL];         // w_attn^T [3D][D]
__device__ __half g_wpt[DMODEL * DMODEL];               // w_proj^T [D][D]

// ---------------------------------------------------------------------------
// helpers
// ---------------------------------------------------------------------------
__device__ __forceinline__ unsigned smem_u32(const void* p) {
    return (unsigned)__cvta_generic_to_shared(p);
}
__device__ __forceinline__ void cp_async16(unsigned s, const void* g) {
    asm volatile("cp.async.cg.shared.global [%0], [%1], 16;\n" :: "r"(s), "l"(g));
}
#define CP_COMMIT() asm volatile("cp.async.commit_group;\n" ::: "memory")
#define CP_WAIT(n)  asm volatile("cp.async.wait_group %0;\n" :: "n"(n) : "memory")

__device__ __forceinline__ unsigned pack2h(float a, float b) {
    __half2 h = __floats2half2_rn(a, b);
    return *(unsigned*)&h;
}
__device__ __forceinline__ void mma_f16s(float* d, const unsigned* a, const unsigned* b) {
    asm volatile(
        "mma.sync.aligned.m16n8k16.row.col.f32.f16.f16.f32 "
        "{%0,%1,%2,%3},{%4,%5,%6,%7},{%8,%9},{%0,%1,%2,%3};\n"
        : "+f"(d[0]), "+f"(d[1]), "+f"(d[2]), "+f"(d[3])
        : "r"(a[0]), "r"(a[1]), "r"(a[2]), "r"(a[3]), "r"(b[0]), "r"(b[1]));
}
__device__ __forceinline__ void ldm_x4(unsigned* r, unsigned addr) {
    asm volatile(
        "ldmatrix.sync.aligned.m8n8.x4.shared.b16 {%0,%1,%2,%3}, [%4];"
        : "=r"(r[0]), "=r"(r[1]), "=r"(r[2]), "=r"(r[3]) : "r"(addr));
}

// ---------------------------------------------------------------------------
// Prepass 1: fp32 -> fp16 (vectorized)
// ---------------------------------------------------------------------------
__global__ __launch_bounds__(256) void f32_to_f16_kernel(
    const float* __restrict__ src, __half* __restrict__ dst, int n4)
{
    int i = blockIdx.x * blockDim.x + threadIdx.x;
    if (i < n4) {
        float4 v = ((const float4*)src)[i];
        __half2 h0 = __floats2half2_rn(v.x, v.y);
        __half2 h1 = __floats2half2_rn(v.z, v.w);
        ((uint2*)dst)[i] = make_uint2(*(unsigned*)&h0, *(unsigned*)&h1);
    }
}

// ---------------------------------------------------------------------------
// Prepass 2: transpose + convert: W [K][N] f32 -> Wt [N][K] f16
// ---------------------------------------------------------------------------
__global__ void transpose_to_f16_kernel(
    const float* __restrict__ src, __half* __restrict__ dst, int K, int N)
{
    __shared__ float t[32][33];
    int n = blockIdx.x * 32 + threadIdx.x;
    int k = blockIdx.y * 32 + threadIdx.y;
    t[threadIdx.y][threadIdx.x] = src[(size_t)k * N + n];
    __syncthreads();
    int no = blockIdx.x * 32 + threadIdx.y;
    int ko = blockIdx.y * 32 + threadIdx.x;
    dst[(size_t)no * K + ko] = __float2half_rn(t[threadIdx.x][threadIdx.y]);
}

// ---------------------------------------------------------------------------
// FP16 mma.sync GEMM: C[M,N] = A[M,K] @ W[K,N] + bias  (Wt pre-transposed [N][K])
// Block tile 128x64, BK=64, 4 warps (warp tile 32x64), 2-stage cp.async.
// 48KB static smem, 128 threads -> 4 independent CTAs/SM (staggered syncs).
// smem rows: 128B, XOR-swizzled (chunk ^= row&7); ldmatrix feeds.
// MODE 0: scatter fp16 into g_qh/g_kh/g_vth (+bias). MODE 1: fp32 C (+bias).
// ---------------------------------------------------------------------------
template <int MODE>
__global__ __launch_bounds__(128, 4) void gemm_f16(
    const float* __restrict__ bias,
    float* __restrict__ C,
    int Kdim, int Ndim)
{
    __shared__ __align__(128) __half As[2][128 * 64];   // 2 x 16KB
    __shared__ __align__(128) __half Bs[2][64 * 64];    // 2 x 8KB

    const __half* A  = (MODE == 0) ? g_hidh  : g_attnh;
    const __half* Wt = (MODE == 0) ? g_wqkvt : g_wpt;

    const int m0 = blockIdx.y * 128;
    const int n0 = blockIdx.x * 64;
    const int tid  = threadIdx.x;
    const int lane = tid & 31;
    const int wid  = tid >> 5;
    const int wr = wid * 32;         // warp row offset (4 warps in M)
    const int g  = lane >> 2;
    const int t2 = (lane & 3) * 2;

    // ldmatrix lane roles
    const int rA  = lane & 15;       // A: row within 16-row pair
    const int cA  = lane >> 4;       // A: k-chunk select (0/1)
    const int selB = lane >> 3;      // B: 0..3
    const int rBo  = ((selB >> 1) << 3) + (lane & 7);
    const int cB   = selB & 1;

    const unsigned sA[2] = { smem_u32(As[0]), smem_u32(As[1]) };
    const unsigned sB[2] = { smem_u32(Bs[0]), smem_u32(Bs[1]) };

    float acc[2][8][4];
#pragma unroll
    for (int i = 0; i < 2; i++)
#pragma unroll
        for (int j = 0; j < 8; j++)
#pragma unroll
            for (int r = 0; r < 4; r++) acc[i][j][r] = 0.0f;

    // Loader: A 128 rows x 8 chunks (8/thread), B 64 rows x 8 chunks (4/thread)
#define LOAD_TILE(KT_, ST_)                                                     \
    _Pragma("unroll")                                                           \
    for (int i_ = 0; i_ < 8; i_++) {                                            \
        const int c_ = tid + i_ * 128;                                          \
        const int row_ = c_ >> 3, ch_ = c_ & 7;                                 \
        const unsigned ph_ = row_ * 128 + (((ch_) ^ (row_ & 7)) << 4);          \
        cp_async16(sA[ST_] + ph_, &A[(size_t)(m0 + row_) * Kdim + (KT_) + ch_ * 8]); \
    }                                                                           \
    _Pragma("unroll")                                                           \
    for (int i_ = 0; i_ < 4; i_++) {                                            \
        const int c_ = tid + i_ * 128;                                          \
        const int row_ = c_ >> 3, ch_ = c_ & 7;                                 \
        const unsigned ph_ = row_ * 128 + (((ch_) ^ (row_ & 7)) << 4);          \
        cp_async16(sB[ST_] + ph_, &Wt[(size_t)(n0 + row_) * Kdim + (KT_) + ch_ * 8]); \
    }

    const int KT = Kdim >> 6;   // 64-wide k tiles
    LOAD_TILE(0, 0);
    CP_COMMIT();

    for (int kt = 0; kt < KT; kt++) {
        const int st = kt & 1;
        CP_WAIT(0);
        __syncthreads();   // tile kt visible; all warps done with buffer st^1

        if (kt + 1 < KT) {
            LOAD_TILE((kt + 1) << 6, st ^ 1);
            CP_COMMIT();
        }

#pragma unroll
        for (int kc = 0; kc < 4; kc++) {
            unsigned af[2][4], bf[8][2];
#pragma unroll
            for (int i = 0; i < 2; i++) {
                const int row = wr + i * 16 + rA;
                const unsigned ph =
                    row * 128 + ((((kc << 1) | cA) ^ (row & 7)) << 4);
                ldm_x4(af[i], sA[st] + ph);
            }
#pragma unroll
            for (int jj = 0; jj < 4; jj++) {
                const int row = jj * 16 + rBo;
                const unsigned ph =
                    row * 128 + ((((kc << 1) | cB) ^ (row & 7)) << 4);
                unsigned q[4];
                ldm_x4(q, sB[st] + ph);
                bf[2 * jj][0]     = q[0];
                bf[2 * jj][1]     = q[1];
                bf[2 * jj + 1][0] = q[2];
                bf[2 * jj + 1][1] = q[3];
            }
#pragma unroll
            for (int i = 0; i < 2; i++)
#pragma unroll
                for (int j = 0; j < 8; j++) mma_f16s(acc[i][j], af[i], bf[j]);
        }
    }

    // epilogue: c0,c1 = (row, 2c),(row, 2c+1); c2,c3 at row+8
#pragma unroll
    for (int i = 0; i < 2; i++) {
#pragma unroll
        for (int rr = 0; rr < 2; rr++) {
            const int row = m0 + wr + i * 16 + g + rr * 8;
#pragma unroll
            for (int j = 0; j < 8; j++) {
                const int col = n0 + j * 8 + t2;
                const float v0 = acc[i][j][rr * 2 + 0] + bias[col];
                const float v1 = acc[i][j][rr * 2 + 1] + bias[col + 1];
                if (MODE == 0) {
                    const int which = col >> 10;       // 0=q,1=k,2=v
                    const int d  = col & 1023;
                    const int h  = d >> 6;
                    const int hd = d & 63;
                    const int b  = row >> 11;
                    const int t  = row & 2047;
                    if (which < 2) {
                        __half* dst = (which == 0) ? g_qh : g_kh;
                        const size_t idx =
                            (((size_t)(b * NHEAD + h)) * SEQ + t) * HDIM + hd;
                        __half2 hv = __floats2half2_rn(v0, v1);
                        *(__half2*)&dst[idx] = hv;
                    } else {
                        const size_t idx =
                            (((size_t)(b * NHEAD + h)) * HDIM + hd) * SEQ + t;
                        g_vth[idx]       = __float2half_rn(v0);
                        g_vth[idx + SEQ] = __float2half_rn(v1);
                    }
                } else {
                    *(float2*)&C[(size_t)row * Ndim + col] = make_float2(v0, v1);
                }
            }
        }
    }
#undef LOAD_TILE
}

// ---------------------------------------------------------------------------
// Causal flash attention, FP16 mma.sync, ldmatrix feeds, key-tile 128.
// Block 128 threads (4 warps), Q tile 64, key tile 128, HD=64.
// K tile [key 128][hd 64] (128B rows); V^T as two 64x64 halves (identical
// layout to R8). Double-buffered cp.async, 64KB dynamic smem, 3 CTAs/SM.
// Halved per-key softmax/sync overhead vs key-tile 64.
// ---------------------------------------------------------------------------
__global__ __launch_bounds__(128, 3) void flash_f16()
{
    extern __shared__ __align__(128) unsigned char fdsm_raw[];
    const unsigned base =
        (smem_u32(fdsm_raw) + 127u) & ~127u;
    // layout: Ks[2] 2x16KB | Vt[2][2] 4x8KB
    const unsigned ksB[2] = { base, base + 16384 };
    const unsigned vtB[2][2] = {
        { base + 32768, base + 40960 },
        { base + 49152, base + 57344 }
    };

    const int qTile = blockIdx.x;
    const int bh    = blockIdx.y;

    const __half* Qh  = g_qh  + (size_t)bh * SEQ * HDIM;
    const __half* Kh  = g_kh  + (size_t)bh * SEQ * HDIM;
    const __half* Vth = g_vth + (size_t)bh * HDIM * SEQ;

    const int tid  = threadIdx.x;
    const int lane = tid & 31;
    const int wid  = tid >> 5;
    const int g    = lane >> 2;
    const int t2   = (lane & 3) * 2;
    const int q0   = qTile * 64;
    const int qr   = q0 + wid * 16 + g;

    const int selB = lane >> 3;
    const int rBo  = ((selB >> 1) << 3) + (lane & 7);
    const int cB   = selB & 1;

    // preload Q fragments (4 k16-chunks over HD=64)
    unsigned qf[4][4];
#pragma unroll
    for (int kc = 0; kc < 4; kc++) {
        const int ko = kc * 16 + t2;
        qf[kc][0] = *(const unsigned*)&Qh[(size_t)qr * HDIM + ko];
        qf[kc][1] = *(const unsigned*)&Qh[(size_t)(qr + 8) * HDIM + ko];
        qf[kc][2] = *(const unsigned*)&Qh[(size_t)qr * HDIM + ko + 8];
        qf[kc][3] = *(const unsigned*)&Qh[(size_t)(qr + 8) * HDIM + ko + 8];
    }

    float oacc[8][4];
#pragma unroll
    for (int j = 0; j < 8; j++)
#pragma unroll
        for (int r = 0; r < 4; r++) oacc[j][r] = 0.0f;
    float m0r = -1e30f, m1r = -1e30f, l0r = 0.0f, l1r = 0.0f;

    // loader: K 128 rows x 8 chunks (8/thread); V halves 64 rows x 8 (4+4/thread)
#define LOAD_KV(K0_, ST_)                                                       \
    _Pragma("unroll")                                                           \
    for (int i_ = 0; i_ < 8; i_++) {                                            \
        const int c_ = tid + i_ * 128;                                          \
        const int r_ = c_ >> 3, ch_ = c_ & 7;                                   \
        const unsigned ph_ = r_ * 128 + (((ch_) ^ (r_ & 7)) << 4);              \
        cp_async16(ksB[ST_] + ph_, &Kh[(size_t)((K0_) + r_) * HDIM + ch_ * 8]); \
    }                                                                           \
    _Pragma("unroll")                                                           \
    for (int hf_ = 0; hf_ < 2; hf_++) {                                         \
        _Pragma("unroll")                                                       \
        for (int i_ = 0; i_ < 4; i_++) {                                        \
            const int c_ = tid + i_ * 128;                                      \
            const int r_ = c_ >> 3, ch_ = c_ & 7;                               \
            const unsigned ph_ = r_ * 128 + (((ch_) ^ (r_ & 7)) << 4);          \
            cp_async16(vtB[ST_][hf_] + ph_,                                     \
                       &Vth[(size_t)r_ * SEQ + (K0_) + hf_ * 64 + ch_ * 8]);    \
        }                                                                       \
    }

    const int ktN = (qTile >> 1) + 1;   // 128-key tiles
    LOAD_KV(0, 0);
    CP_COMMIT();

    for (int kt = 0; kt < ktN; kt++) {
        const int st = kt & 1;
        CP_WAIT(0);
        __syncthreads();   // tile kt resident & visible

        if (kt + 1 < ktN) {
            LOAD_KV((kt + 1) * 128, st ^ 1);
            CP_COMMIT();
        }

        // S = Q @ K^T  (16 n8 j-tiles = 128 keys)
        float sacc[16][4];
#pragma unroll
        for (int j = 0; j < 16; j++)
#pragma unroll
            for (int r = 0; r < 4; r++) sacc[j][r] = 0.0f;

#pragma unroll
        for (int kc = 0; kc < 4; kc++) {
            unsigned bf[16][2];
#pragma unroll
            for (int jj = 0; jj < 8; jj++) {
                const int row = jj * 16 + rBo;
                const unsigned ph =
                    row * 128 + ((((kc << 1) | cB) ^ (row & 7)) << 4);
                unsigned q[4];
                ldm_x4(q, ksB[st] + ph);
                bf[2 * jj][0]     = q[0];
                bf[2 * jj][1]     = q[1];
                bf[2 * jj + 1][0] = q[2];
                bf[2 * jj + 1][1] = q[3];
            }
#pragma unroll
            for (int j = 0; j < 16; j++) mma_f16s(sacc[j], qf[kc], bf[j]);
        }

        // scale + causal mask (last tile only; global indices)
        const float scl = 0.125f;   // 1/sqrt(64)
        if (kt == ktN - 1) {
            const int r0 = q0 + wid * 16 + g;
            const int r1 = r0 + 8;
            const int kbase = kt * 128;
#pragma unroll
            for (int j = 0; j < 16; j++) {
                const int c = kbase + j * 8 + t2;
                sacc[j][0] = (c     > r0) ? -1e30f : sacc[j][0] * scl;
                sacc[j][1] = (c + 1 > r0) ? -1e30f : sacc[j][1] * scl;
                sacc[j][2] = (c     > r1) ? -1e30f : sacc[j][2] * scl;
                sacc[j][3] = (c + 1 > r1) ? -1e30f : sacc[j][3] * scl;
            }
        } else {
#pragma unroll
            for (int j = 0; j < 16; j++)
#pragma unroll
                for (int r = 0; r < 4; r++) sacc[j][r] *= scl;
        }

        // online softmax (rows owned by 4-lane groups; xor-reduce over 1,2)
        float rm0 = -1e30f, rm1 = -1e30f;
#pragma unroll
        for (int j = 0; j < 16; j++) {
            rm0 = fmaxf(rm0, fmaxf(sacc[j][0], sacc[j][1]));
            rm1 = fmaxf(rm1, fmaxf(sacc[j][2], sacc[j][3]));
        }
#pragma unroll
        for (int s = 1; s < 4; s <<= 1) {
            rm0 = fmaxf(rm0, __shfl_xor_sync(0xffffffffu, rm0, s));
            rm1 = fmaxf(rm1, __shfl_xor_sync(0xffffffffu, rm1, s));
        }
        const float mn0 = fmaxf(m0r, rm0);
        const float mn1 = fmaxf(m1r, rm1);
        const float al0 = __expf(m0r - mn0);
        const float al1 = __expf(m1r - mn1);
        float rs0 = 0.0f, rs1 = 0.0f;
#pragma unroll
        for (int j = 0; j < 16; j++) {
            sacc[j][0] = __expf(sacc[j][0] - mn0);
            sacc[j][1] = __expf(sacc[j][1] - mn0);
            sacc[j][2] = __expf(sacc[j][2] - mn1);
            sacc[j][3] = __expf(sacc[j][3] - mn1);
            rs0 += sacc[j][0] + sacc[j][1];
            rs1 += sacc[j][2] + sacc[j][3];
        }
#pragma unroll
        for (int s = 1; s < 4; s <<= 1) {
            rs0 += __shfl_xor_sync(0xffffffffu, rs0, s);
            rs1 += __shfl_xor_sync(0xffffffffu, rs1, s);
        }
        l0r = l0r * al0 + rs0;
        l1r = l1r * al1 + rs1;
        m0r = mn0;
        m1r = mn1;
#pragma unroll
        for (int j = 0; j < 8; j++) {
            oacc[j][0] *= al0;
            oacc[j][1] *= al0;
            oacc[j][2] *= al1;
            oacc[j][3] *= al1;
        }

        // O += P @ V : 8 k16-chunks over 128 keys; V half = kc>>2
#pragma unroll
        for (int kc = 0; kc < 8; kc++) {
            unsigned af[4];
            af[0] = pack2h(sacc[2 * kc][0],     sacc[2 * kc][1]);
            af[1] = pack2h(sacc[2 * kc][2],     sacc[2 * kc][3]);
            af[2] = pack2h(sacc[2 * kc + 1][0], sacc[2 * kc + 1][1]);
            af[3] = pack2h(sacc[2 * kc + 1][2], sacc[2 * kc + 1][3]);
            const unsigned vbase = vtB[st][kc >> 2];
            const int kci = kc & 3;
            unsigned bf[8][2];
#pragma unroll
            for (int jj = 0; jj < 4; jj++) {
                const int row = jj * 16 + rBo;
                const unsigned ph =
                    row * 128 + ((((kci << 1) | cB) ^ (row & 7)) << 4);
                unsigned q[4];
                ldm_x4(q, vbase + ph);
                bf[2 * jj][0]     = q[0];
                bf[2 * jj][1]     = q[1];
                bf[2 * jj + 1][0] = q[2];
                bf[2 * jj + 1][1] = q[3];
            }
#pragma unroll
            for (int j = 0; j < 8; j++) mma_f16s(oacc[j], af, bf[j]);
        }
        __syncthreads();   // all warps done with buffer st before refill
    }
#undef LOAD_KV

    // write merged-head output [B,T,D] as fp16 (proj consumes fp16)
    const int b = bh >> 4;
    const int h = bh & 15;
    const float il0 = 1.0f / l0r;
    const float il1 = 1.0f / l1r;
    const int t0 = q0 + wid * 16 + g;
    __half* base0 = g_attnh + ((size_t)(b * SEQ + t0)) * DMODEL + h * HDIM;
    __half* base1 = g_attnh + ((size_t)(b * SEQ + t0 + 8)) * DMODEL + h * HDIM;
#pragma unroll
    for (int j = 0; j < 8; j++) {
        const int c = j * 8 + t2;
        __half2 h0 = __floats2half2_rn(oacc[j][0] * il0, oacc[j][1] * il0);
        __half2 h1 = __floats2half2_rn(oacc[j][2] * il1, oacc[j][3] * il1);
        *(__half2*)&base0[c] = h0;
        *(__half2*)&base1[c] = h1;
    }
}

// ---------------------------------------------------------------------------
// kernel_launch
// inputs: 0 hidden_states [B,T,D] f32, 1 w_attn [D,3D], 2 b_attn [3D],
//         3 w_proj [D,D], 4 b_proj [D]; output [B,T,D] f32
// ---------------------------------------------------------------------------
extern "C" void kernel_launch(void* const* d_in, const int* in_sizes, int n_in,
                              void* d_out, int out_size)
{
    const float* hidden = (const float*)d_in[0];
    const float* w_attn = (const float*)d_in[1];
    const float* b_attn = (const float*)d_in[2];
    const float* w_proj = (const float*)d_in[3];
    const float* b_proj = (const float*)d_in[4];
    float* out = (float*)d_out;

    const int FDSM = 65536 + 128;   // flash: 64KB payload + align slack
    cudaFuncSetAttribute(flash_f16, cudaFuncAttributeMaxDynamicSharedMemorySize, FDSM);

    // 0) prepass: fp16 convert + weight transpose
    {
        __half* d_hid; cudaGetSymbolAddress((void**)&d_hid, g_hidh);
        __half* d_wq;  cudaGetSymbolAddress((void**)&d_wq,  g_wqkvt);
        __half* d_wp;  cudaGetSymbolAddress((void**)&d_wp,  g_wpt);
        f32_to_f16_kernel<<<(MROWS * DMODEL / 4 + 255) / 256, 256>>>(
            hidden, d_hid, MROWS * DMODEL / 4);
        transpose_to_f16_kernel<<<dim3(3 * DMODEL / 32, DMODEL / 32), dim3(32, 32)>>>(
            w_attn, d_wq, DMODEL, 3 * DMODEL);
        transpose_to_f16_kernel<<<dim3(DMODEL / 32, DMODEL / 32), dim3(32, 32)>>>(
            w_proj, d_wp, DMODEL, DMODEL);
    }

    // 1) QKV GEMM + bias + head split (128x64 blocks, 4 CTAs/SM)
    gemm_f16<0><<<dim3(3 * DMODEL / 64, MROWS / 128), 128>>>(
        b_attn, nullptr, DMODEL, 3 * DMODEL);

    // 2) causal flash attention (key-tile 128)
    flash_f16<<<dim3(SEQ / 64, BATCH * NHEAD), 128, FDSM>>>();

    // 3) output projection + bias (fp32 out)
    gemm_f16<1><<<dim3(DMODEL / 64, MROWS / 128), 128>>>(
        b_proj, out, DMODEL, DMODEL);
}